// round 14
// baseline (speedup 1.0000x reference)
#include <cuda_runtime.h>
#include <cuda_fp16.h>
#include <stdint.h>

// ---------------------------------------------------------------------------
// HeteroGraphSAGE, 2 layers, 4 node types, 8 relations.  fp16 data plane:
// x0/h/aggr stored fp16 (node tables = 90MB -> L2-resident gathers).
// GEMM = fp16 x fp16 single pass (A err 2^-12, W err 2^-12 -> total ~3.4e-4
// vs 1e-3 threshold; measured 1.69e-4 with exact W in R13).
// agg[d] = Wr * (inv[d] * sum_e w_e * x[src]) -> CSR gather (no atomics);
// one K-concat GEMM per dst type (template NCH).
// ---------------------------------------------------------------------------

#define NU 200000
#define NP 100000
#define NC 2000
#define NQ 50000
#define NTOT 352000
#define HID 128

#define NROWS 802000
#define ETOT  2400000
#define NWCHUNK 24

#define LDS 72              // fp16 elems per smem row (64 data + 8 pad -> 144B)
#define LDSB 144
#define TILE_B (128 * LDSB)          // 18432 B
#define SMEM_BYTES (2 * TILE_B)      // A, W = 36864 B (occupancy 2)

// device globals (allocation-free scratch)
__device__ __half g_x16[(size_t)NTOT * HID];   // x0 in fp16 (concatenated)
__device__ __half g_h16[(size_t)NTOT * HID];   // hidden in fp16
__device__ __half g_a16[(size_t)NROWS * HID];  // aggr in fp16
__device__ int    g_cnt[NROWS];
__device__ int    g_rowptr[NROWS + 1];
__device__ int    g_cursor[NROWS];
__device__ int    g_srcg[ETOT];
__device__ float  g_wg[ETOT];
__device__ int    g_bsums[512];
__device__ float  g_wsum[2 * 4 * HID * HID];
__device__ float  g_bsum[2 * 4 * HID];
__device__ __half g_w16[NWCHUNK * HID * HID];  // weights fp16

// ---------------------------------------------------------------------------
// PTX helpers
// ---------------------------------------------------------------------------
#define LDSM4(R, addr)                                                          \
    asm volatile("ldmatrix.sync.aligned.m8n8.x4.shared.b16 {%0,%1,%2,%3}, [%4];" \
                 : "=r"((R)[0]), "=r"((R)[1]), "=r"((R)[2]), "=r"((R)[3])        \
                 : "r"(addr))

#define MMAF16(C, A, B0, B1)                                                    \
    asm volatile("mma.sync.aligned.m16n8k16.row.col.f32.f16.f16.f32 "           \
                 "{%0,%1,%2,%3},{%4,%5,%6,%7},{%8,%9},{%0,%1,%2,%3};"           \
                 : "+f"((C)[0]), "+f"((C)[1]), "+f"((C)[2]), "+f"((C)[3])        \
                 : "r"((A)[0]), "r"((A)[1]), "r"((A)[2]), "r"((A)[3]),           \
                   "r"(B0), "r"(B1))

__device__ __forceinline__ uint32_t pack_h2(__half a, __half b)
{
    __half2 p = __halves2half2(a, b);
    return *reinterpret_cast<uint32_t*>(&p);
}

// ---------------------------------------------------------------------------
// Multi-chunk fp16 tensor-core GEMM (single pass):
//   C = bias + sum_ch A_ch @ W_ch^T
// NCH = chunks (template). L0=1: relu + write fp16 h; L0=0: write fp32 out.
// Block tile 128x128, 8 warps (4m x 2n), occ 2.
// ---------------------------------------------------------------------------
struct GemmArgs {
    const __half *A0, *A1, *A2, *A3;
    const __half *W0, *W1, *W2, *W3;
};

template <int NCH, int L0>
__global__ void __launch_bounds__(256, 2)
gemm_mma(GemmArgs p, const float* __restrict__ bias,
         float* __restrict__ C32, __half* __restrict__ C16, int n)
{
    extern __shared__ __half smem[];
    uint32_t sb = (uint32_t)__cvta_generic_to_shared(smem);

    const int tid  = threadIdx.x;
    const int lane = tid & 31;
    const int warp = tid >> 5;
    const int wm = warp >> 1;
    const int wn = warp & 1;
    const int bm = blockIdx.x * 128;

    float c[2][8][4];
#pragma unroll
    for (int i = 0; i < 2; i++)
#pragma unroll
        for (int j = 0; j < 8; j++)
#pragma unroll
            for (int q = 0; q < 4; q++) c[i][j][q] = 0.f;

#pragma unroll
    for (int ch = 0; ch < NCH; ch++) {
        const __half* A = (ch == 0) ? p.A0 : (ch == 1) ? p.A1 : (ch == 2) ? p.A2 : p.A3;
        const __half* W = (ch == 0) ? p.W0 : (ch == 1) ? p.W1 : (ch == 2) ? p.W2 : p.W3;

        for (int kb = 0; kb < 128; kb += 64) {
            // ---- fills: pure 16B copies ----
            const uint4 z = make_uint4(0, 0, 0, 0);
#pragma unroll
            for (int it = 0; it < 4; it++) {
                int idx = tid + it * 256;          // granule 0..1023
                int r   = idx >> 3;                // row 0..127
                int kc  = (idx & 7) << 3;          // 8 halves = 16B
                int row = bm + r;
                size_t ga = (size_t)row * HID + kb + kc;
                size_t gw = (size_t)r * HID + kb + kc;
                size_t so = (size_t)r * LDS + kc;
                *(uint4*)(smem + so) = (row < n) ? *(const uint4*)(A + ga) : z;
                *(uint4*)(smem + 128 * LDS + so) = *(const uint4*)(W + gw);
            }
            __syncthreads();

            // ---- 4 k-steps of 16, single MMA pass ----
#pragma unroll
            for (int ks = 0; ks < 4; ks++) {
                uint32_t a[2][4], b[4][4];
#pragma unroll
                for (int i = 0; i < 2; i++) {
                    int r   = wm * 32 + i * 16 + (lane & 15);
                    int kby = ks * 32 + ((lane >> 4) << 4);
                    LDSM4(a[i], sb + r * LDSB + kby);
                }
#pragma unroll
                for (int pq = 0; pq < 4; pq++) {
                    int nr  = wn * 64 + (2 * pq + (lane >> 4)) * 8 + (lane & 7);
                    int kby = ks * 32 + ((lane >> 3) & 1) * 16;
                    LDSM4(b[pq], sb + TILE_B + nr * LDSB + kby);
                }
#pragma unroll
                for (int i = 0; i < 2; i++)
#pragma unroll
                    for (int j = 0; j < 8; j++) {
                        const uint32_t* bb = b[j >> 1] + (j & 1) * 2;
                        MMAF16(c[i][j], a[i], bb[0], bb[1]);
                    }
            }
            __syncthreads();
        }
    }

    // ---- epilogue ----
    const int g  = lane >> 2;
    const int tq = lane & 3;
#pragma unroll
    for (int i = 0; i < 2; i++) {
#pragma unroll
        for (int half = 0; half < 2; half++) {
            int row = bm + wm * 32 + i * 16 + half * 8 + g;
            if (row >= n) continue;
#pragma unroll
            for (int j = 0; j < 8; j++) {
                int col = wn * 64 + j * 8 + tq * 2;
                float vx = c[i][j][half * 2 + 0] + bias[col];
                float vy = c[i][j][half * 2 + 1] + bias[col + 1];
                if (L0) {
                    vx = fmaxf(vx, 0.f);
                    vy = fmaxf(vy, 0.f);
                    *(uint32_t*)(C16 + (size_t)row * HID + col) =
                        pack_h2(__float2half(vx), __float2half(vy));
                } else {
                    *(float2*)(C32 + (size_t)row * HID + col) = make_float2(vx, vy);
                }
            }
        }
    }
}

// ---------------------------------------------------------------------------
// merged CSR count (one launch)
// ---------------------------------------------------------------------------
__global__ void csr_count(const int* __restrict__ eb, const int* __restrict__ es,
                          const int* __restrict__ em, const int* __restrict__ ein,
                          int* __restrict__ cnt)
{
    int e = blockIdx.x * 256 + threadIdx.x;
    if (e >= ETOT) return;
    const int* dstp; int rowOff, le;
    if      (e <  500000) { dstp = eb + 500000;  rowOff = 0;      le = e; }
    else if (e < 1000000) { dstp = eb;           rowOff = 100000; le = e - 500000; }
    else if (e < 1300000) { dstp = es + 300000;  rowOff = 300000; le = e - 1000000; }
    else if (e < 1600000) { dstp = es;           rowOff = 350000; le = e - 1300000; }
    else if (e < 1900000) { dstp = em + 300000;  rowOff = 550000; le = e - 1600000; }
    else if (e < 2200000) { dstp = em;           rowOff = 650000; le = e - 1900000; }
    else if (e < 2300000) { dstp = ein + 100000; rowOff = 700000; le = e - 2200000; }
    else                  { dstp = ein;          rowOff = 702000; le = e - 2300000; }
    atomicAdd(&cnt[rowOff + dstp[le]], 1);
}

__global__ void scan1_kernel(const int* __restrict__ cnt, int* __restrict__ rowptr,
                             int* __restrict__ bsums, int n)
{
    __shared__ int wsums[8];
    int base = blockIdx.x * 4096 + threadIdx.x * 16;
    int v[16];
    int s = 0;
#pragma unroll
    for (int i = 0; i < 16; i++) {
        v[i] = (base + i < n) ? cnt[base + i] : 0;
        s += v[i];
    }
    int lane = threadIdx.x & 31, w = threadIdx.x >> 5;
    int ps = s;
#pragma unroll
    for (int o = 1; o < 32; o <<= 1) {
        int t = __shfl_up_sync(0xffffffffu, ps, o);
        if (lane >= o) ps += t;
    }
    if (lane == 31) wsums[w] = ps;
    __syncthreads();
    if (w == 0) {
        int t = (lane < 8) ? wsums[lane] : 0;
#pragma unroll
        for (int o = 1; o < 8; o <<= 1) {
            int u = __shfl_up_sync(0xffffffffu, t, o);
            if (lane >= o) t += u;
        }
        if (lane < 8) wsums[lane] = t;
    }
    __syncthreads();
    int excl = ps - s + (w ? wsums[w - 1] : 0);
    int run = excl;
#pragma unroll
    for (int i = 0; i < 16; i++) {
        if (base + i < n) rowptr[base + i] = run;
        run += v[i];
    }
    if (threadIdx.x == 0) bsums[blockIdx.x] = wsums[7];
}

__global__ void scan2_kernel(int* __restrict__ bsums, int nb)
{
    if (threadIdx.x == 0 && blockIdx.x == 0) {
        int run = 0;
        for (int i = 0; i < nb; i++) {
            int t = bsums[i];
            bsums[i] = run;
            run += t;
        }
    }
}

__global__ void scan3_kernel(int* __restrict__ rowptr, const int* __restrict__ bsums,
                             int* __restrict__ cursor, int n)
{
    int base = blockIdx.x * 4096 + threadIdx.x * 16;
    int off = bsums[blockIdx.x];
#pragma unroll
    for (int i = 0; i < 16; i++)
        if (base + i < n) {
            int v = rowptr[base + i] + off;
            rowptr[base + i] = v;
            cursor[base + i] = v;
        }
    if (blockIdx.x == 0 && threadIdx.x == 0) rowptr[n] = ETOT;
}

// ---------------------------------------------------------------------------
// merged CSR fill (one launch)
// ---------------------------------------------------------------------------
__global__ void csr_fill(const int* __restrict__ eb, const int* __restrict__ es,
                         const int* __restrict__ em, const int* __restrict__ ein,
                         const float* __restrict__ w0, const float* __restrict__ w1,
                         const float* __restrict__ w2, const float* __restrict__ w3,
                         const float* __restrict__ w4, const float* __restrict__ w5,
                         const float* __restrict__ w6, const float* __restrict__ w7,
                         int* __restrict__ cursor, int* __restrict__ srcg,
                         float* __restrict__ wg)
{
    int e = blockIdx.x * 256 + threadIdx.x;
    if (e >= ETOT) return;
    const int *dstp, *srcp; const float* ewp; int rowOff, le;
    if      (e <  500000) { dstp = eb + 500000;  srcp = eb;           ewp = w0; rowOff = 0;      le = e; }
    else if (e < 1000000) { dstp = eb;           srcp = eb + 500000;  ewp = w1; rowOff = 100000; le = e - 500000; }
    else if (e < 1300000) { dstp = es + 300000;  srcp = es;           ewp = w2; rowOff = 300000; le = e - 1000000; }
    else if (e < 1600000) { dstp = es;           srcp = es + 300000;  ewp = w3; rowOff = 350000; le = e - 1300000; }
    else if (e < 1900000) { dstp = em + 300000;  srcp = em;           ewp = w4; rowOff = 550000; le = e - 1600000; }
    else if (e < 2200000) { dstp = em;           srcp = em + 300000;  ewp = w5; rowOff = 650000; le = e - 1900000; }
    else if (e < 2300000) { dstp = ein + 100000; srcp = ein;          ewp = w6; rowOff = 700000; le = e - 2200000; }
    else                  { dstp = ein;          srcp = ein + 100000; ewp = w7; rowOff = 702000; le = e - 2300000; }
    int slot = atomicAdd(&cursor[rowOff + dstp[le]], 1);
    srcg[slot] = srcp[le];
    wg[slot]   = ewp[le];
}

// ---------------------------------------------------------------------------
// Combined Wl / bias per (layer, dst type).
// ---------------------------------------------------------------------------
__global__ void wsum_kernel(const float* __restrict__ W1l, const float* __restrict__ b1,
                            const float* __restrict__ W2l, const float* __restrict__ b2,
                            float* __restrict__ wsum, float* __restrict__ bsum)
{
    const int dstT[8] = {1, 0, 3, 0, 1, 3, 2, 1};
    int idx = blockIdx.x * blockDim.x + threadIdx.x;
    if (idx >= 2 * 4 * HID * HID) return;
    int l  = idx / (4 * HID * HID);
    int r  = idx % (4 * HID * HID);
    int d  = r / (HID * HID);
    int ij = r % (HID * HID);
    const float* W = l ? W2l : W1l;
    float s = 0.f;
#pragma unroll
    for (int t = 0; t < 8; t++)
        if (dstT[t] == d) s += W[t * HID * HID + ij];
    wsum[idx] = s;
    if (ij < HID) {
        const float* B = l ? b2 : b1;
        float sb = 0.f;
#pragma unroll
        for (int t = 0; t < 8; t++)
            if (dstT[t] == d) sb += B[t * HID + ij];
        bsum[(l * 4 + d) * HID + ij] = sb;
    }
}

// ---------------------------------------------------------------------------
// Convert all 24 weight chunks to fp16.
// ---------------------------------------------------------------------------
__global__ void wconv_kernel(const float* __restrict__ wsum,
                             const float* __restrict__ W1r,
                             const float* __restrict__ W2r,
                             __half* __restrict__ w16)
{
    int idx = blockIdx.x * blockDim.x + threadIdx.x;
    if (idx >= NWCHUNK * HID * HID) return;
    int c  = idx >> 14;
    int ij = idx & 16383;
    float v = (c < 8) ? wsum[idx]
            : (c < 16) ? W1r[(c - 8) * HID * HID + ij]
                       : W2r[(c - 16) * HID * HID + ij];
    w16[idx] = __float2half(v);
}

// ---------------------------------------------------------------------------
// Convert x0 tables -> concatenated fp16 buffer (once per launch).
// ---------------------------------------------------------------------------
__global__ void xhalf_kernel(const float* __restrict__ xu, const float* __restrict__ xp,
                             const float* __restrict__ xc, const float* __restrict__ xq,
                             __half* __restrict__ x16)
{
    int i = blockIdx.x * 256 + threadIdx.x;          // 8-elem group index
    if (i >= NTOT * 16) return;
    int row = i >> 4;
    int c8  = (i & 15) << 3;
    const float* x;
    int lrow;
    if      (row < NU)           { x = xu; lrow = row; }
    else if (row < NU + NP)      { x = xp; lrow = row - NU; }
    else if (row < NU + NP + NC) { x = xc; lrow = row - NU - NP; }
    else                         { x = xq; lrow = row - NU - NP - NC; }
    float4 v0 = *(const float4*)(x + (size_t)lrow * HID + c8);
    float4 v1 = *(const float4*)(x + (size_t)lrow * HID + c8 + 4);
    uint4 o;
    o.x = pack_h2(__float2half(v0.x), __float2half(v0.y));
    o.y = pack_h2(__float2half(v0.z), __float2half(v0.w));
    o.z = pack_h2(__float2half(v1.x), __float2half(v1.y));
    o.w = pack_h2(__float2half(v1.z), __float2half(v1.w));
    *(uint4*)(x16 + (size_t)row * HID + c8) = o;
}

// ---------------------------------------------------------------------------
// Merged CSR gather: one warp per (relation,dst) row over ALL rows.
// fp16 source, fp32 accumulate, fp16 aggr out. 2-edge unroll.
// ---------------------------------------------------------------------------
__global__ void gather_kernel(const __half* __restrict__ xbase,
                              const int* __restrict__ rowptr,
                              const int* __restrict__ srcg,
                              const float* __restrict__ wg,
                              __half* __restrict__ a16)
{
    int row = (blockIdx.x * blockDim.x + threadIdx.x) >> 5;
    int lane = threadIdx.x & 31;
    if (row >= NROWS) return;
    const size_t OU = 0, OP = (size_t)NU * HID, OC = (size_t)(NU + NP) * HID,
                 OQ = (size_t)(NU + NP + NC) * HID;
    size_t xo = (row <  100000) ? OU
              : (row <  300000) ? OP
              : (row <  350000) ? OU
              : (row <  550000) ? OQ
              : (row <  650000) ? OQ
              : (row <  702000) ? OP : OC;
    const __half* x = xbase + xo;

    int e0 = rowptr[row], e1 = rowptr[row + 1];
    float4 acc = make_float4(0.f, 0.f, 0.f, 0.f);
    int e = e0;
    for (; e + 1 < e1; e += 2) {
        int   s0 = srcg[e],  s1 = srcg[e + 1];
        float w0 = wg[e],    w1 = wg[e + 1];
        uint2 u0 = *((const uint2*)(x + (size_t)s0 * HID) + lane);
        uint2 u1 = *((const uint2*)(x + (size_t)s1 * HID) + lane);
        float2 a0 = __half22float2(*reinterpret_cast<__half2*>(&u0.x));
        float2 b0 = __half22float2(*reinterpret_cast<__half2*>(&u0.y));
        float2 a1 = __half22float2(*reinterpret_cast<__half2*>(&u1.x));
        float2 b1 = __half22float2(*reinterpret_cast<__half2*>(&u1.y));
        acc.x += w0 * a0.x + w1 * a1.x;
        acc.y += w0 * a0.y + w1 * a1.y;
        acc.z += w0 * b0.x + w1 * b1.x;
        acc.w += w0 * b0.y + w1 * b1.y;
    }
    if (e < e1) {
        int s0 = srcg[e];
        float w0 = wg[e];
        uint2 u0 = *((const uint2*)(x + (size_t)s0 * HID) + lane);
        float2 a0 = __half22float2(*reinterpret_cast<__half2*>(&u0.x));
        float2 b0 = __half22float2(*reinterpret_cast<__half2*>(&u0.y));
        acc.x += w0 * a0.x;
        acc.y += w0 * a0.y;
        acc.z += w0 * b0.x;
        acc.w += w0 * b0.y;
    }
    float invd = 1.f / fmaxf((float)(e1 - e0), 1.f);
    acc.x *= invd; acc.y *= invd; acc.z *= invd; acc.w *= invd;

    uint2 o;
    o.x = pack_h2(__float2half(acc.x), __float2half(acc.y));
    o.y = pack_h2(__float2half(acc.z), __float2half(acc.w));
    *((uint2*)(a16 + (size_t)row * HID) + lane) = o;
}

// ---------------------------------------------------------------------------
// Host launch
// ---------------------------------------------------------------------------
extern "C" void kernel_launch(void* const* d_in, const int* in_sizes, int n_in,
                              void* d_out, int out_size)
{
    (void)in_sizes; (void)n_in; (void)out_size;

    static const int rowOffR[8] = {0, 100000, 300000, 350000, 550000, 650000, 700000, 702000};
    static const int relForDst[4][3] = { {1, 3, -1}, {0, 4, 7}, {6, -1, -1}, {2, 5, -1} };
    static const int nRelForDst[4]   = { 2, 3, 1, 2 };
    static const int    nodeN[4]   = {NU, NP, NC, NQ};
    static const size_t nodeOff[4] = {0, NU, NU + NP, NU + NP + NC};

    cudaFuncSetAttribute(gemm_mma<2,0>, cudaFuncAttributeMaxDynamicSharedMemorySize, SMEM_BYTES);
    cudaFuncSetAttribute(gemm_mma<3,0>, cudaFuncAttributeMaxDynamicSharedMemorySize, SMEM_BYTES);
    cudaFuncSetAttribute(gemm_mma<4,0>, cudaFuncAttributeMaxDynamicSharedMemorySize, SMEM_BYTES);
    cudaFuncSetAttribute(gemm_mma<2,1>, cudaFuncAttributeMaxDynamicSharedMemorySize, SMEM_BYTES);
    cudaFuncSetAttribute(gemm_mma<3,1>, cudaFuncAttributeMaxDynamicSharedMemorySize, SMEM_BYTES);
    cudaFuncSetAttribute(gemm_mma<4,1>, cudaFuncAttributeMaxDynamicSharedMemorySize, SMEM_BYTES);

    float *wsum, *bsum, *wg;
    __half *x16, *h16, *a16, *w16;
    int *cnt, *rowptr, *cursor, *srcg, *bsums;
    cudaGetSymbolAddress((void**)&x16,    g_x16);
    cudaGetSymbolAddress((void**)&h16,    g_h16);
    cudaGetSymbolAddress((void**)&a16,    g_a16);
    cudaGetSymbolAddress((void**)&cnt,    g_cnt);
    cudaGetSymbolAddress((void**)&rowptr, g_rowptr);
    cudaGetSymbolAddress((void**)&cursor, g_cursor);
    cudaGetSymbolAddress((void**)&srcg,   g_srcg);
    cudaGetSymbolAddress((void**)&wg,     g_wg);
    cudaGetSymbolAddress((void**)&bsums,  g_bsums);
    cudaGetSymbolAddress((void**)&wsum,   g_wsum);
    cudaGetSymbolAddress((void**)&bsum,   g_bsum);
    cudaGetSymbolAddress((void**)&w16,    g_w16);

    const float* xu = (const float*)d_in[0];
    const float* xp = (const float*)d_in[1];
    const float* xc = (const float*)d_in[2];
    const float* xq = (const float*)d_in[3];
    const float* W1l = (const float*)d_in[4];
    const float* b1  = (const float*)d_in[5];
    const float* W1r = (const float*)d_in[6];
    const float* W2l = (const float*)d_in[7];
    const float* b2  = (const float*)d_in[8];
    const float* W2r = (const float*)d_in[9];
    const int* eb  = (const int*)d_in[18];
    const int* es  = (const int*)d_in[19];
    const int* em  = (const int*)d_in[20];
    const int* ein = (const int*)d_in[21];
    float* out = (float*)d_out;

    cudaStream_t st = 0;
    const int NSCAN = (NROWS + 4095) / 4096;

    // ---- CSR build (layer-invariant) ----
    cudaMemsetAsync(cnt, 0, NROWS * sizeof(int), st);
    csr_count<<<(ETOT + 255) / 256, 256, 0, st>>>(eb, es, em, ein, cnt);
    scan1_kernel<<<NSCAN, 256, 0, st>>>(cnt, rowptr, bsums, NROWS);
    scan2_kernel<<<1, 32, 0, st>>>(bsums, NSCAN);
    scan3_kernel<<<NSCAN, 256, 0, st>>>(rowptr, bsums, cursor, NROWS);
    csr_fill<<<(ETOT + 255) / 256, 256, 0, st>>>(
        eb, es, em, ein,
        (const float*)d_in[10], (const float*)d_in[11], (const float*)d_in[12],
        (const float*)d_in[13], (const float*)d_in[14], (const float*)d_in[15],
        (const float*)d_in[16], (const float*)d_in[17],
        cursor, srcg, wg);

    // ---- weights + x16 ----
    wsum_kernel<<<(2 * 4 * HID * HID + 255) / 256, 256, 0, st>>>(W1l, b1, W2l, b2, wsum, bsum);
    wconv_kernel<<<(NWCHUNK * HID * HID + 255) / 256, 256, 0, st>>>(wsum, W1r, W2r, w16);
    xhalf_kernel<<<(NTOT * 16 + 255) / 256, 256, 0, st>>>(xu, xp, xc, xq, x16);

    // ---- two layers ----
    for (int layer = 0; layer < 2; layer++) {
        const __half* src = layer ? h16 : x16;
        gather_kernel<<<(NROWS * 32 + 255) / 256, 256, 0, st>>>(
            src, rowptr, srcg, wg, a16);

        for (int d = 0; d < 4; d++) {
            const __half *Ap[3]  = {nullptr, nullptr, nullptr};
            const __half *Wp[4]  = {nullptr, nullptr, nullptr, nullptr};
            Wp[0] = w16 + (size_t)(layer * 4 + d) * HID * HID;
            for (int q = 0; q < nRelForDst[d]; q++) {
                int t = relForDst[d][q];
                Ap[q] = a16 + (size_t)rowOffR[t] * HID;
                Wp[q + 1] = w16 + (size_t)(8 + layer * 8 + t) * HID * HID;
            }
            GemmArgs p;
            p.A0 = src + nodeOff[d] * HID;
            p.A1 = Ap[0]; p.A2 = Ap[1]; p.A3 = Ap[2];
            p.W0 = Wp[0]; p.W1 = Wp[1]; p.W2 = Wp[2]; p.W3 = Wp[3];
            int nch = 1 + nRelForDst[d];
            float* C32 = layer ? (out + nodeOff[d] * HID) : nullptr;
            __half* C16 = layer ? nullptr : (h16 + nodeOff[d] * HID);
            const float* bs = bsum + (layer * 4 + d) * HID;
            int grid = (nodeN[d] + 127) / 128;
            if (layer == 0) {
                if (nch == 2)      gemm_mma<2,1><<<grid, 256, SMEM_BYTES, st>>>(p, bs, C32, C16, nodeN[d]);
                else if (nch == 3) gemm_mma<3,1><<<grid, 256, SMEM_BYTES, st>>>(p, bs, C32, C16, nodeN[d]);
                else               gemm_mma<4,1><<<grid, 256, SMEM_BYTES, st>>>(p, bs, C32, C16, nodeN[d]);
            } else {
                if (nch == 2)      gemm_mma<2,0><<<grid, 256, SMEM_BYTES, st>>>(p, bs, C32, C16, nodeN[d]);
                else if (nch == 3) gemm_mma<3,0><<<grid, 256, SMEM_BYTES, st>>>(p, bs, C32, C16, nodeN[d]);
                else               gemm_mma<4,0><<<grid, 256, SMEM_BYTES, st>>>(p, bs, C32, C16, nodeN[d]);
            }
        }
    }
}

// round 15
// speedup vs baseline: 1.2094x; 1.2094x over previous
#include <cuda_runtime.h>
#include <cuda_fp16.h>
#include <stdint.h>

// ---------------------------------------------------------------------------
// HeteroGraphSAGE, 2 layers, 4 node types, 8 relations.  fp16 data plane:
// x0/h/aggr stored fp16 (node tables = 90MB -> L2-resident gathers).
// GEMM = fp16 x (fp16-hi + fp16-lo W), 2 MMA passes (R14 showed 1-pass is
// NOT faster: mainloop is fill-latency-bound, extra MMAs are free).
// R15: double-buffered cp.async pipeline, 2 x 55.3KB stages -> occ 2 kept.
// agg[d] = Wr * (inv[d] * sum_e w_e * x[src]) -> CSR gather (no atomics);
// one K-concat GEMM per dst type (template NCH).
// ---------------------------------------------------------------------------

#define NU 200000
#define NP 100000
#define NC 2000
#define NQ 50000
#define NTOT 352000
#define HID 128

#define NROWS 802000
#define ETOT  2400000
#define NWCHUNK 24

#define LDS 72              // fp16 elems per smem row (64 data + 8 pad -> 144B)
#define LDSB 144
#define TILE_B (128 * LDSB)          // 18432 B
#define STAGE_B (3 * TILE_B)         // A, Wh, Wl = 55296 B
#define SMEM_BYTES (2 * STAGE_B)     // double buffer = 110592 B (occ 2: 221KB/SM)

// device globals (allocation-free scratch)
__device__ __half g_x16[(size_t)NTOT * HID];   // x0 in fp16 (concatenated)
__device__ __half g_h16[(size_t)NTOT * HID];   // hidden in fp16
__device__ __half g_a16[(size_t)NROWS * HID];  // aggr in fp16
__device__ int    g_cnt[NROWS];
__device__ int    g_rowptr[NROWS + 1];
__device__ int    g_cursor[NROWS];
__device__ int    g_srcg[ETOT];
__device__ float  g_wg[ETOT];
__device__ int    g_bsums[512];
__device__ float  g_wsum[2 * 4 * HID * HID];
__device__ float  g_bsum[2 * 4 * HID];
__device__ __half g_wh[NWCHUNK * HID * HID];   // weights fp16 hi
__device__ __half g_wl[NWCHUNK * HID * HID];   // weights fp16 residual

// ---------------------------------------------------------------------------
// PTX helpers
// ---------------------------------------------------------------------------
#define LDSM4(R, addr)                                                          \
    asm volatile("ldmatrix.sync.aligned.m8n8.x4.shared.b16 {%0,%1,%2,%3}, [%4];" \
                 : "=r"((R)[0]), "=r"((R)[1]), "=r"((R)[2]), "=r"((R)[3])        \
                 : "r"(addr))

#define MMAF16(C, A, B0, B1)                                                    \
    asm volatile("mma.sync.aligned.m16n8k16.row.col.f32.f16.f16.f32 "           \
                 "{%0,%1,%2,%3},{%4,%5,%6,%7},{%8,%9},{%0,%1,%2,%3};"           \
                 : "+f"((C)[0]), "+f"((C)[1]), "+f"((C)[2]), "+f"((C)[3])        \
                 : "r"((A)[0]), "r"((A)[1]), "r"((A)[2]), "r"((A)[3]),           \
                   "r"(B0), "r"(B1))

__device__ __forceinline__ void cpa16(uint32_t dst, const void* src, uint32_t sz)
{
    asm volatile("cp.async.cg.shared.global [%0], [%1], 16, %2;"
                 :: "r"(dst), "l"(src), "r"(sz) : "memory");
}

__device__ __forceinline__ uint32_t pack_h2(__half a, __half b)
{
    __half2 p = __halves2half2(a, b);
    return *reinterpret_cast<uint32_t*>(&p);
}

// ---------------------------------------------------------------------------
// Multi-chunk fp16 tensor-core GEMM (W split hi+lo, 2 passes), double-buffered
// cp.async pipeline: C = bias + sum_ch A_ch @ (Wh_ch + Wl_ch)^T
// NCH = chunks. L0=1: relu + write fp16 h; L0=0: write fp32 out.
// Block tile 128x128, 8 warps (4m x 2n), occ 2.
// ---------------------------------------------------------------------------
struct GemmArgs {
    const __half *A0, *A1, *A2, *A3;
    const __half *W0h, *W0l, *W1h, *W1l, *W2h, *W2l, *W3h, *W3l;
};

__device__ __forceinline__ void issue_stage(const GemmArgs& p, int s, uint32_t bufb,
                                            int bm, int n, int tid)
{
    int ch = s >> 1;
    const __half* A  = (ch == 0) ? p.A0  : (ch == 1) ? p.A1  : (ch == 2) ? p.A2  : p.A3;
    const __half* Wh = (ch == 0) ? p.W0h : (ch == 1) ? p.W1h : (ch == 2) ? p.W2h : p.W3h;
    const __half* Wl = (ch == 0) ? p.W0l : (ch == 1) ? p.W1l : (ch == 2) ? p.W2l : p.W3l;
    int kb = (s & 1) * 64;

#pragma unroll
    for (int it = 0; it < 4; it++) {
        int idx = tid + it * 256;          // granule 0..1023
        int r   = idx >> 3;                // row 0..127
        int kc  = (idx & 7) << 3;          // 8 halves = 16B
        int grow = bm + r;
        int rowc = (grow < n) ? grow : (n - 1);
        uint32_t ok = (grow < n) ? 16u : 0u;
        size_t ga = (size_t)rowc * HID + kb + kc;
        size_t gw = (size_t)r * HID + kb + kc;
        uint32_t so = r * LDSB + kc * 2;
        cpa16(bufb + so,              A  + ga, ok);
        cpa16(bufb + TILE_B + so,     Wh + gw, 16u);
        cpa16(bufb + 2 * TILE_B + so, Wl + gw, 16u);
    }
    asm volatile("cp.async.commit_group;" ::: "memory");
}

template <int NCH, int L0>
__global__ void __launch_bounds__(256, 2)
gemm_mma(GemmArgs p, const float* __restrict__ bias,
         float* __restrict__ C32, __half* __restrict__ C16, int n)
{
    extern __shared__ __half smem[];
    uint32_t sb = (uint32_t)__cvta_generic_to_shared(smem);

    const int tid  = threadIdx.x;
    const int lane = tid & 31;
    const int warp = tid >> 5;
    const int wm = warp >> 1;
    const int wn = warp & 1;
    const int bm = blockIdx.x * 128;

    float c[2][8][4];
#pragma unroll
    for (int i = 0; i < 2; i++)
#pragma unroll
        for (int j = 0; j < 8; j++)
#pragma unroll
            for (int q = 0; q < 4; q++) c[i][j][q] = 0.f;

    const int nst = NCH * 2;

    issue_stage(p, 0, sb, bm, n, tid);
    issue_stage(p, 1, sb + STAGE_B, bm, n, tid);

    for (int s = 0; s < nst; s++) {
        if (s + 1 < nst)
            asm volatile("cp.async.wait_group 1;" ::: "memory");
        else
            asm volatile("cp.async.wait_group 0;" ::: "memory");
        __syncthreads();

        uint32_t bufb = sb + (s & 1) * STAGE_B;

        // ---- 4 k-steps of 16, 2 MMA passes ----
#pragma unroll
        for (int ks = 0; ks < 4; ks++) {
            uint32_t a[2][4], bh[4][4], bl[4][4];
#pragma unroll
            for (int i = 0; i < 2; i++) {
                int r   = wm * 32 + i * 16 + (lane & 15);
                int kby = ks * 32 + ((lane >> 4) << 4);
                LDSM4(a[i], bufb + r * LDSB + kby);
            }
#pragma unroll
            for (int pq = 0; pq < 4; pq++) {
                int nr  = wn * 64 + (2 * pq + (lane >> 4)) * 8 + (lane & 7);
                int kby = ks * 32 + ((lane >> 3) & 1) * 16;
                uint32_t ad = bufb + TILE_B + nr * LDSB + kby;
                LDSM4(bh[pq], ad);
                LDSM4(bl[pq], ad + TILE_B);
            }
#pragma unroll
            for (int i = 0; i < 2; i++)
#pragma unroll
                for (int j = 0; j < 8; j++) {
                    const uint32_t* b = bh[j >> 1] + (j & 1) * 2;
                    MMAF16(c[i][j], a[i], b[0], b[1]);
                }
#pragma unroll
            for (int i = 0; i < 2; i++)
#pragma unroll
                for (int j = 0; j < 8; j++) {
                    const uint32_t* b = bl[j >> 1] + (j & 1) * 2;
                    MMAF16(c[i][j], a[i], b[0], b[1]);
                }
        }
        __syncthreads();
        if (s + 2 < nst)
            issue_stage(p, s + 2, sb + (s & 1) * STAGE_B, bm, n, tid);
    }

    // ---- epilogue ----
    const int g  = lane >> 2;
    const int tq = lane & 3;
#pragma unroll
    for (int i = 0; i < 2; i++) {
#pragma unroll
        for (int half = 0; half < 2; half++) {
            int row = bm + wm * 32 + i * 16 + half * 8 + g;
            if (row >= n) continue;
#pragma unroll
            for (int j = 0; j < 8; j++) {
                int col = wn * 64 + j * 8 + tq * 2;
                float vx = c[i][j][half * 2 + 0] + bias[col];
                float vy = c[i][j][half * 2 + 1] + bias[col + 1];
                if (L0) {
                    vx = fmaxf(vx, 0.f);
                    vy = fmaxf(vy, 0.f);
                    *(uint32_t*)(C16 + (size_t)row * HID + col) =
                        pack_h2(__float2half(vx), __float2half(vy));
                } else {
                    *(float2*)(C32 + (size_t)row * HID + col) = make_float2(vx, vy);
                }
            }
        }
    }
}

// ---------------------------------------------------------------------------
// merged CSR count (one launch)
// ---------------------------------------------------------------------------
__global__ void csr_count(const int* __restrict__ eb, const int* __restrict__ es,
                          const int* __restrict__ em, const int* __restrict__ ein,
                          int* __restrict__ cnt)
{
    int e = blockIdx.x * 256 + threadIdx.x;
    if (e >= ETOT) return;
    const int* dstp; int rowOff, le;
    if      (e <  500000) { dstp = eb + 500000;  rowOff = 0;      le = e; }
    else if (e < 1000000) { dstp = eb;           rowOff = 100000; le = e - 500000; }
    else if (e < 1300000) { dstp = es + 300000;  rowOff = 300000; le = e - 1000000; }
    else if (e < 1600000) { dstp = es;           rowOff = 350000; le = e - 1300000; }
    else if (e < 1900000) { dstp = em + 300000;  rowOff = 550000; le = e - 1600000; }
    else if (e < 2200000) { dstp = em;           rowOff = 650000; le = e - 1900000; }
    else if (e < 2300000) { dstp = ein + 100000; rowOff = 700000; le = e - 2200000; }
    else                  { dstp = ein;          rowOff = 702000; le = e - 2300000; }
    atomicAdd(&cnt[rowOff + dstp[le]], 1);
}

__global__ void scan1_kernel(const int* __restrict__ cnt, int* __restrict__ rowptr,
                             int* __restrict__ bsums, int n)
{
    __shared__ int wsums[8];
    int base = blockIdx.x * 4096 + threadIdx.x * 16;
    int v[16];
    int s = 0;
#pragma unroll
    for (int i = 0; i < 16; i++) {
        v[i] = (base + i < n) ? cnt[base + i] : 0;
        s += v[i];
    }
    int lane = threadIdx.x & 31, w = threadIdx.x >> 5;
    int ps = s;
#pragma unroll
    for (int o = 1; o < 32; o <<= 1) {
        int t = __shfl_up_sync(0xffffffffu, ps, o);
        if (lane >= o) ps += t;
    }
    if (lane == 31) wsums[w] = ps;
    __syncthreads();
    if (w == 0) {
        int t = (lane < 8) ? wsums[lane] : 0;
#pragma unroll
        for (int o = 1; o < 8; o <<= 1) {
            int u = __shfl_up_sync(0xffffffffu, t, o);
            if (lane >= o) t += u;
        }
        if (lane < 8) wsums[lane] = t;
    }
    __syncthreads();
    int excl = ps - s + (w ? wsums[w - 1] : 0);
    int run = excl;
#pragma unroll
    for (int i = 0; i < 16; i++) {
        if (base + i < n) rowptr[base + i] = run;
        run += v[i];
    }
    if (threadIdx.x == 0) bsums[blockIdx.x] = wsums[7];
}

__global__ void scan2_kernel(int* __restrict__ bsums, int nb)
{
    if (threadIdx.x == 0 && blockIdx.x == 0) {
        int run = 0;
        for (int i = 0; i < nb; i++) {
            int t = bsums[i];
            bsums[i] = run;
            run += t;
        }
    }
}

__global__ void scan3_kernel(int* __restrict__ rowptr, const int* __restrict__ bsums,
                             int* __restrict__ cursor, int n)
{
    int base = blockIdx.x * 4096 + threadIdx.x * 16;
    int off = bsums[blockIdx.x];
#pragma unroll
    for (int i = 0; i < 16; i++)
        if (base + i < n) {
            int v = rowptr[base + i] + off;
            rowptr[base + i] = v;
            cursor[base + i] = v;
        }
    if (blockIdx.x == 0 && threadIdx.x == 0) rowptr[n] = ETOT;
}

// ---------------------------------------------------------------------------
// merged CSR fill (one launch)
// ---------------------------------------------------------------------------
__global__ void csr_fill(const int* __restrict__ eb, const int* __restrict__ es,
                         const int* __restrict__ em, const int* __restrict__ ein,
                         const float* __restrict__ w0, const float* __restrict__ w1,
                         const float* __restrict__ w2, const float* __restrict__ w3,
                         const float* __restrict__ w4, const float* __restrict__ w5,
                         const float* __restrict__ w6, const float* __restrict__ w7,
                         int* __restrict__ cursor, int* __restrict__ srcg,
                         float* __restrict__ wg)
{
    int e = blockIdx.x * 256 + threadIdx.x;
    if (e >= ETOT) return;
    const int *dstp, *srcp; const float* ewp; int rowOff, le;
    if      (e <  500000) { dstp = eb + 500000;  srcp = eb;           ewp = w0; rowOff = 0;      le = e; }
    else if (e < 1000000) { dstp = eb;           srcp = eb + 500000;  ewp = w1; rowOff = 100000; le = e - 500000; }
    else if (e < 1300000) { dstp = es + 300000;  srcp = es;           ewp = w2; rowOff = 300000; le = e - 1000000; }
    else if (e < 1600000) { dstp = es;           srcp = es + 300000;  ewp = w3; rowOff = 350000; le = e - 1300000; }
    else if (e < 1900000) { dstp = em + 300000;  srcp = em;           ewp = w4; rowOff = 550000; le = e - 1600000; }
    else if (e < 2200000) { dstp = em;           srcp = em + 300000;  ewp = w5; rowOff = 650000; le = e - 1900000; }
    else if (e < 2300000) { dstp = ein + 100000; srcp = ein;          ewp = w6; rowOff = 700000; le = e - 2200000; }
    else                  { dstp = ein;          srcp = ein + 100000; ewp = w7; rowOff = 702000; le = e - 2300000; }
    int slot = atomicAdd(&cursor[rowOff + dstp[le]], 1);
    srcg[slot] = srcp[le];
    wg[slot]   = ewp[le];
}

// ---------------------------------------------------------------------------
// Combined Wl / bias per (layer, dst type).
// ---------------------------------------------------------------------------
__global__ void wsum_kernel(const float* __restrict__ W1l, const float* __restrict__ b1,
                            const float* __restrict__ W2l, const float* __restrict__ b2,
                            float* __restrict__ wsum, float* __restrict__ bsum)
{
    const int dstT[8] = {1, 0, 3, 0, 1, 3, 2, 1};
    int idx = blockIdx.x * blockDim.x + threadIdx.x;
    if (idx >= 2 * 4 * HID * HID) return;
    int l  = idx / (4 * HID * HID);
    int r  = idx % (4 * HID * HID);
    int d  = r / (HID * HID);
    int ij = r % (HID * HID);
    const float* W = l ? W2l : W1l;
    float s = 0.f;
#pragma unroll
    for (int t = 0; t < 8; t++)
        if (dstT[t] == d) s += W[t * HID * HID + ij];
    wsum[idx] = s;
    if (ij < HID) {
        const float* B = l ? b2 : b1;
        float sb = 0.f;
#pragma unroll
        for (int t = 0; t < 8; t++)
            if (dstT[t] == d) sb += B[t * HID + ij];
        bsum[(l * 4 + d) * HID + ij] = sb;
    }
}

// ---------------------------------------------------------------------------
// Pre-split all 24 weight chunks into fp16 hi + fp16 residual.
// ---------------------------------------------------------------------------
__global__ void wsplit_kernel(const float* __restrict__ wsum,
                              const float* __restrict__ W1r,
                              const float* __restrict__ W2r,
                              __half* __restrict__ wh, __half* __restrict__ wl)
{
    int idx = blockIdx.x * blockDim.x + threadIdx.x;
    if (idx >= NWCHUNK * HID * HID) return;
    int c  = idx >> 14;
    int ij = idx & 16383;
    float v = (c < 8) ? wsum[idx]
            : (c < 16) ? W1r[(c - 8) * HID * HID + ij]
                       : W2r[(c - 16) * HID * HID + ij];
    __half h = __float2half(v);
    wh[idx] = h;
    wl[idx] = __float2half(v - __half2float(h));
}

// ---------------------------------------------------------------------------
// Convert x0 tables -> concatenated fp16 buffer (once per launch).
// ---------------------------------------------------------------------------
__global__ void xhalf_kernel(const float* __restrict__ xu, const float* __restrict__ xp,
                             const float* __restrict__ xc, const float* __restrict__ xq,
                             __half* __restrict__ x16)
{
    int i = blockIdx.x * 256 + threadIdx.x;          // 8-elem group index
    if (i >= NTOT * 16) return;
    int row = i >> 4;
    int c8  = (i & 15) << 3;
    const float* x;
    int lrow;
    if      (row < NU)           { x = xu; lrow = row; }
    else if (row < NU + NP)      { x = xp; lrow = row - NU; }
    else if (row < NU + NP + NC) { x = xc; lrow = row - NU - NP; }
    else                         { x = xq; lrow = row - NU - NP - NC; }
    float4 v0 = *(const float4*)(x + (size_t)lrow * HID + c8);
    float4 v1 = *(const float4*)(x + (size_t)lrow * HID + c8 + 4);
    uint4 o;
    o.x = pack_h2(__float2half(v0.x), __float2half(v0.y));
    o.y = pack_h2(__float2half(v0.z), __float2half(v0.w));
    o.z = pack_h2(__float2half(v1.x), __float2half(v1.y));
    o.w = pack_h2(__float2half(v1.z), __float2half(v1.w));
    *(uint4*)(x16 + (size_t)row * HID + c8) = o;
}

// ---------------------------------------------------------------------------
// Merged CSR gather: one warp per (relation,dst) row over ALL rows.
// fp16 source, fp32 accumulate, fp16 aggr out. 2-edge unroll.
// ---------------------------------------------------------------------------
__global__ void gather_kernel(const __half* __restrict__ xbase,
                              const int* __restrict__ rowptr,
                              const int* __restrict__ srcg,
                              const float* __restrict__ wg,
                              __half* __restrict__ a16)
{
    int row = (blockIdx.x * blockDim.x + threadIdx.x) >> 5;
    int lane = threadIdx.x & 31;
    if (row >= NROWS) return;
    const size_t OU = 0, OP = (size_t)NU * HID, OC = (size_t)(NU + NP) * HID,
                 OQ = (size_t)(NU + NP + NC) * HID;
    size_t xo = (row <  100000) ? OU
              : (row <  300000) ? OP
              : (row <  350000) ? OU
              : (row <  550000) ? OQ
              : (row <  650000) ? OQ
              : (row <  702000) ? OP : OC;
    const __half* x = xbase + xo;

    int e0 = rowptr[row], e1 = rowptr[row + 1];
    float4 acc = make_float4(0.f, 0.f, 0.f, 0.f);
    int e = e0;
    for (; e + 1 < e1; e += 2) {
        int   s0 = srcg[e],  s1 = srcg[e + 1];
        float w0 = wg[e],    w1 = wg[e + 1];
        uint2 u0 = *((const uint2*)(x + (size_t)s0 * HID) + lane);
        uint2 u1 = *((const uint2*)(x + (size_t)s1 * HID) + lane);
        float2 a0 = __half22float2(*reinterpret_cast<__half2*>(&u0.x));
        float2 b0 = __half22float2(*reinterpret_cast<__half2*>(&u0.y));
        float2 a1 = __half22float2(*reinterpret_cast<__half2*>(&u1.x));
        float2 b1 = __half22float2(*reinterpret_cast<__half2*>(&u1.y));
        acc.x += w0 * a0.x + w1 * a1.x;
        acc.y += w0 * a0.y + w1 * a1.y;
        acc.z += w0 * b0.x + w1 * b1.x;
        acc.w += w0 * b0.y + w1 * b1.y;
    }
    if (e < e1) {
        int s0 = srcg[e];
        float w0 = wg[e];
        uint2 u0 = *((const uint2*)(x + (size_t)s0 * HID) + lane);
        float2 a0 = __half22float2(*reinterpret_cast<__half2*>(&u0.x));
        float2 b0 = __half22float2(*reinterpret_cast<__half2*>(&u0.y));
        acc.x += w0 * a0.x;
        acc.y += w0 * a0.y;
        acc.z += w0 * b0.x;
        acc.w += w0 * b0.y;
    }
    float invd = 1.f / fmaxf((float)(e1 - e0), 1.f);
    acc.x *= invd; acc.y *= invd; acc.z *= invd; acc.w *= invd;

    uint2 o;
    o.x = pack_h2(__float2half(acc.x), __float2half(acc.y));
    o.y = pack_h2(__float2half(acc.z), __float2half(acc.w));
    *((uint2*)(a16 + (size_t)row * HID) + lane) = o;
}

// ---------------------------------------------------------------------------
// Host launch
// ---------------------------------------------------------------------------
extern "C" void kernel_launch(void* const* d_in, const int* in_sizes, int n_in,
                              void* d_out, int out_size)
{
    (void)in_sizes; (void)n_in; (void)out_size;

    static const int rowOffR[8] = {0, 100000, 300000, 350000, 550000, 650000, 700000, 702000};
    static const int relForDst[4][3] = { {1, 3, -1}, {0, 4, 7}, {6, -1, -1}, {2, 5, -1} };
    static const int nRelForDst[4]   = { 2, 3, 1, 2 };
    static const int    nodeN[4]   = {NU, NP, NC, NQ};
    static const size_t nodeOff[4] = {0, NU, NU + NP, NU + NP + NC};

    cudaFuncSetAttribute(gemm_mma<2,0>, cudaFuncAttributeMaxDynamicSharedMemorySize, SMEM_BYTES);
    cudaFuncSetAttribute(gemm_mma<3,0>, cudaFuncAttributeMaxDynamicSharedMemorySize, SMEM_BYTES);
    cudaFuncSetAttribute(gemm_mma<4,0>, cudaFuncAttributeMaxDynamicSharedMemorySize, SMEM_BYTES);
    cudaFuncSetAttribute(gemm_mma<2,1>, cudaFuncAttributeMaxDynamicSharedMemorySize, SMEM_BYTES);
    cudaFuncSetAttribute(gemm_mma<3,1>, cudaFuncAttributeMaxDynamicSharedMemorySize, SMEM_BYTES);
    cudaFuncSetAttribute(gemm_mma<4,1>, cudaFuncAttributeMaxDynamicSharedMemorySize, SMEM_BYTES);

    float *wsum, *bsum, *wg;
    __half *x16, *h16, *a16, *wh, *wl;
    int *cnt, *rowptr, *cursor, *srcg, *bsums;
    cudaGetSymbolAddress((void**)&x16,    g_x16);
    cudaGetSymbolAddress((void**)&h16,    g_h16);
    cudaGetSymbolAddress((void**)&a16,    g_a16);
    cudaGetSymbolAddress((void**)&cnt,    g_cnt);
    cudaGetSymbolAddress((void**)&rowptr, g_rowptr);
    cudaGetSymbolAddress((void**)&cursor, g_cursor);
    cudaGetSymbolAddress((void**)&srcg,   g_srcg);
    cudaGetSymbolAddress((void**)&wg,     g_wg);
    cudaGetSymbolAddress((void**)&bsums,  g_bsums);
    cudaGetSymbolAddress((void**)&wsum,   g_wsum);
    cudaGetSymbolAddress((void**)&bsum,   g_bsum);
    cudaGetSymbolAddress((void**)&wh,     g_wh);
    cudaGetSymbolAddress((void**)&wl,     g_wl);

    const float* xu = (const float*)d_in[0];
    const float* xp = (const float*)d_in[1];
    const float* xc = (const float*)d_in[2];
    const float* xq = (const float*)d_in[3];
    const float* W1l = (const float*)d_in[4];
    const float* b1  = (const float*)d_in[5];
    const float* W1r = (const float*)d_in[6];
    const float* W2l = (const float*)d_in[7];
    const float* b2  = (const float*)d_in[8];
    const float* W2r = (const float*)d_in[9];
    const int* eb  = (const int*)d_in[18];
    const int* es  = (const int*)d_in[19];
    const int* em  = (const int*)d_in[20];
    const int* ein = (const int*)d_in[21];
    float* out = (float*)d_out;

    cudaStream_t st = 0;
    const int NSCAN = (NROWS + 4095) / 4096;

    // ---- CSR build (layer-invariant) ----
    cudaMemsetAsync(cnt, 0, NROWS * sizeof(int), st);
    csr_count<<<(ETOT + 255) / 256, 256, 0, st>>>(eb, es, em, ein, cnt);
    scan1_kernel<<<NSCAN, 256, 0, st>>>(cnt, rowptr, bsums, NROWS);
    scan2_kernel<<<1, 32, 0, st>>>(bsums, NSCAN);
    scan3_kernel<<<NSCAN, 256, 0, st>>>(rowptr, bsums, cursor, NROWS);
    csr_fill<<<(ETOT + 255) / 256, 256, 0, st>>>(
        eb, es, em, ein,
        (const float*)d_in[10], (const float*)d_in[11], (const float*)d_in[12],
        (const float*)d_in[13], (const float*)d_in[14], (const float*)d_in[15],
        (const float*)d_in[16], (const float*)d_in[17],
        cursor, srcg, wg);

    // ---- weights + x16 ----
    wsum_kernel<<<(2 * 4 * HID * HID + 255) / 256, 256, 0, st>>>(W1l, b1, W2l, b2, wsum, bsum);
    wsplit_kernel<<<(NWCHUNK * HID * HID + 255) / 256, 256, 0, st>>>(wsum, W1r, W2r, wh, wl);
    xhalf_kernel<<<(NTOT * 16 + 255) / 256, 256, 0, st>>>(xu, xp, xc, xq, x16);

    // ---- two layers ----
    for (int layer = 0; layer < 2; layer++) {
        const __half* src = layer ? h16 : x16;
        gather_kernel<<<(NROWS * 32 + 255) / 256, 256, 0, st>>>(
            src, rowptr, srcg, wg, a16);

        for (int d = 0; d < 4; d++) {
            const __half *Ap[3]  = {nullptr, nullptr, nullptr};
            const __half *Whp[4] = {nullptr, nullptr, nullptr, nullptr};
            const __half *Wlp[4] = {nullptr, nullptr, nullptr, nullptr};
            Whp[0] = wh + (size_t)(layer * 4 + d) * HID * HID;
            Wlp[0] = wl + (size_t)(layer * 4 + d) * HID * HID;
            for (int q = 0; q < nRelForDst[d]; q++) {
                int t = relForDst[d][q];
                Ap[q] = a16 + (size_t)rowOffR[t] * HID;
                Whp[q + 1] = wh + (size_t)(8 + layer * 8 + t) * HID * HID;
                Wlp[q + 1] = wl + (size_t)(8 + layer * 8 + t) * HID * HID;
            }
            GemmArgs p;
            p.A0 = src + nodeOff[d] * HID;
            p.A1 = Ap[0]; p.A2 = Ap[1]; p.A3 = Ap[2];
            p.W0h = Whp[0]; p.W0l = Wlp[0];
            p.W1h = Whp[1]; p.W1l = Wlp[1];
            p.W2h = Whp[2]; p.W2l = Wlp[2];
            p.W3h = Whp[3]; p.W3l = Wlp[3];
            int nch = 1 + nRelForDst[d];
            float* C32 = layer ? (out + nodeOff[d] * HID) : nullptr;
            __half* C16 = layer ? nullptr : (h16 + nodeOff[d] * HID);
            const float* bs = bsum + (layer * 4 + d) * HID;
            int grid = (nodeN[d] + 127) / 128;
            if (layer == 0) {
                if (nch == 2)      gemm_mma<2,1><<<grid, 256, SMEM_BYTES, st>>>(p, bs, C32, C16, nodeN[d]);
                else if (nch == 3) gemm_mma<3,1><<<grid, 256, SMEM_BYTES, st>>>(p, bs, C32, C16, nodeN[d]);
                else               gemm_mma<4,1><<<grid, 256, SMEM_BYTES, st>>>(p, bs, C32, C16, nodeN[d]);
            } else {
                if (nch == 2)      gemm_mma<2,0><<<grid, 256, SMEM_BYTES, st>>>(p, bs, C32, C16, nodeN[d]);
                else if (nch == 3) gemm_mma<3,0><<<grid, 256, SMEM_BYTES, st>>>(p, bs, C32, C16, nodeN[d]);
                else               gemm_mma<4,0><<<grid, 256, SMEM_BYTES, st>>>(p, bs, C32, C16, nodeN[d]);
            }
        }
    }
}

// round 16
// speedup vs baseline: 1.5200x; 1.2568x over previous
#include <cuda_runtime.h>
#include <cuda_fp16.h>
#include <stdint.h>

// ---------------------------------------------------------------------------
// HeteroGraphSAGE, 2 layers, 4 node types, 8 relations.  fp16 data plane:
// x0/h/aggr stored fp16 (node tables L2-resident for random gathers).
// GEMM = fp16 x (fp16-hi + fp16-lo W), 2 MMA passes, double-buffered cp.async
// pipeline at occupancy 2 (proven R15). R16: gather 2 rows/warp with uint4
// lane loads; prep/CSR chains and the 4 per-dst GEMMs overlapped on streams.
// ---------------------------------------------------------------------------

#define NU 200000
#define NP 100000
#define NC 2000
#define NQ 50000
#define NTOT 352000
#define HID 128

#define NROWS 802000
#define ETOT  2400000
#define NWCHUNK 24

#define LDS 72
#define LDSB 144
#define TILE_B (128 * LDSB)          // 18432 B
#define STAGE_B (3 * TILE_B)         // A, Wh, Wl = 55296 B
#define SMEM_BYTES (2 * STAGE_B)     // double buffer = 110592 B (occ 2)

// device globals (allocation-free scratch)
__device__ __half g_x16[(size_t)NTOT * HID];
__device__ __half g_h16[(size_t)NTOT * HID];
__device__ __half g_a16[(size_t)NROWS * HID];
__device__ int    g_cnt[NROWS];
__device__ int    g_rowptr[NROWS + 1];
__device__ int    g_cursor[NROWS];
__device__ int    g_srcg[ETOT];
__device__ float  g_wg[ETOT];
__device__ int    g_bsums[512];
__device__ float  g_wsum[2 * 4 * HID * HID];
__device__ float  g_bsum[2 * 4 * HID];
__device__ __half g_wh[NWCHUNK * HID * HID];
__device__ __half g_wl[NWCHUNK * HID * HID];

// ---------------------------------------------------------------------------
// PTX helpers
// ---------------------------------------------------------------------------
#define LDSM4(R, addr)                                                          \
    asm volatile("ldmatrix.sync.aligned.m8n8.x4.shared.b16 {%0,%1,%2,%3}, [%4];" \
                 : "=r"((R)[0]), "=r"((R)[1]), "=r"((R)[2]), "=r"((R)[3])        \
                 : "r"(addr))

#define MMAF16(C, A, B0, B1)                                                    \
    asm volatile("mma.sync.aligned.m16n8k16.row.col.f32.f16.f16.f32 "           \
                 "{%0,%1,%2,%3},{%4,%5,%6,%7},{%8,%9},{%0,%1,%2,%3};"           \
                 : "+f"((C)[0]), "+f"((C)[1]), "+f"((C)[2]), "+f"((C)[3])        \
                 : "r"((A)[0]), "r"((A)[1]), "r"((A)[2]), "r"((A)[3]),           \
                   "r"(B0), "r"(B1))

__device__ __forceinline__ void cpa16(uint32_t dst, const void* src, uint32_t sz)
{
    asm volatile("cp.async.cg.shared.global [%0], [%1], 16, %2;"
                 :: "r"(dst), "l"(src), "r"(sz) : "memory");
}

__device__ __forceinline__ uint32_t pack_h2(__half a, __half b)
{
    __half2 p = __halves2half2(a, b);
    return *reinterpret_cast<uint32_t*>(&p);
}

// ---------------------------------------------------------------------------
// GEMM (unchanged from R15)
// ---------------------------------------------------------------------------
struct GemmArgs {
    const __half *A0, *A1, *A2, *A3;
    const __half *W0h, *W0l, *W1h, *W1l, *W2h, *W2l, *W3h, *W3l;
};

__device__ __forceinline__ void issue_stage(const GemmArgs& p, int s, uint32_t bufb,
                                            int bm, int n, int tid)
{
    int ch = s >> 1;
    const __half* A  = (ch == 0) ? p.A0  : (ch == 1) ? p.A1  : (ch == 2) ? p.A2  : p.A3;
    const __half* Wh = (ch == 0) ? p.W0h : (ch == 1) ? p.W1h : (ch == 2) ? p.W2h : p.W3h;
    const __half* Wl = (ch == 0) ? p.W0l : (ch == 1) ? p.W1l : (ch == 2) ? p.W2l : p.W3l;
    int kb = (s & 1) * 64;

#pragma unroll
    for (int it = 0; it < 4; it++) {
        int idx = tid + it * 256;
        int r   = idx >> 3;
        int kc  = (idx & 7) << 3;
        int grow = bm + r;
        int rowc = (grow < n) ? grow : (n - 1);
        uint32_t ok = (grow < n) ? 16u : 0u;
        size_t ga = (size_t)rowc * HID + kb + kc;
        size_t gw = (size_t)r * HID + kb + kc;
        uint32_t so = r * LDSB + kc * 2;
        cpa16(bufb + so,              A  + ga, ok);
        cpa16(bufb + TILE_B + so,     Wh + gw, 16u);
        cpa16(bufb + 2 * TILE_B + so, Wl + gw, 16u);
    }
    asm volatile("cp.async.commit_group;" ::: "memory");
}

template <int NCH, int L0>
__global__ void __launch_bounds__(256, 2)
gemm_mma(GemmArgs p, const float* __restrict__ bias,
         float* __restrict__ C32, __half* __restrict__ C16, int n)
{
    extern __shared__ __half smem[];
    uint32_t sb = (uint32_t)__cvta_generic_to_shared(smem);

    const int tid  = threadIdx.x;
    const int lane = tid & 31;
    const int warp = tid >> 5;
    const int wm = warp >> 1;
    const int wn = warp & 1;
    const int bm = blockIdx.x * 128;

    float c[2][8][4];
#pragma unroll
    for (int i = 0; i < 2; i++)
#pragma unroll
        for (int j = 0; j < 8; j++)
#pragma unroll
            for (int q = 0; q < 4; q++) c[i][j][q] = 0.f;

    const int nst = NCH * 2;

    issue_stage(p, 0, sb, bm, n, tid);
    issue_stage(p, 1, sb + STAGE_B, bm, n, tid);

    for (int s = 0; s < nst; s++) {
        if (s + 1 < nst)
            asm volatile("cp.async.wait_group 1;" ::: "memory");
        else
            asm volatile("cp.async.wait_group 0;" ::: "memory");
        __syncthreads();

        uint32_t bufb = sb + (s & 1) * STAGE_B;

#pragma unroll
        for (int ks = 0; ks < 4; ks++) {
            uint32_t a[2][4], bh[4][4], bl[4][4];
#pragma unroll
            for (int i = 0; i < 2; i++) {
                int r   = wm * 32 + i * 16 + (lane & 15);
                int kby = ks * 32 + ((lane >> 4) << 4);
                LDSM4(a[i], bufb + r * LDSB + kby);
            }
#pragma unroll
            for (int pq = 0; pq < 4; pq++) {
                int nr  = wn * 64 + (2 * pq + (lane >> 4)) * 8 + (lane & 7);
                int kby = ks * 32 + ((lane >> 3) & 1) * 16;
                uint32_t ad = bufb + TILE_B + nr * LDSB + kby;
                LDSM4(bh[pq], ad);
                LDSM4(bl[pq], ad + TILE_B);
            }
#pragma unroll
            for (int i = 0; i < 2; i++)
#pragma unroll
                for (int j = 0; j < 8; j++) {
                    const uint32_t* b = bh[j >> 1] + (j & 1) * 2;
                    MMAF16(c[i][j], a[i], b[0], b[1]);
                }
#pragma unroll
            for (int i = 0; i < 2; i++)
#pragma unroll
                for (int j = 0; j < 8; j++) {
                    const uint32_t* b = bl[j >> 1] + (j & 1) * 2;
                    MMAF16(c[i][j], a[i], b[0], b[1]);
                }
        }
        __syncthreads();
        if (s + 2 < nst)
            issue_stage(p, s + 2, sb + (s & 1) * STAGE_B, bm, n, tid);
    }

    // ---- epilogue ----
    const int g  = lane >> 2;
    const int tq = lane & 3;
#pragma unroll
    for (int i = 0; i < 2; i++) {
#pragma unroll
        for (int half = 0; half < 2; half++) {
            int row = bm + wm * 32 + i * 16 + half * 8 + g;
            if (row >= n) continue;
#pragma unroll
            for (int j = 0; j < 8; j++) {
                int col = wn * 64 + j * 8 + tq * 2;
                float vx = c[i][j][half * 2 + 0] + bias[col];
                float vy = c[i][j][half * 2 + 1] + bias[col + 1];
                if (L0) {
                    vx = fmaxf(vx, 0.f);
                    vy = fmaxf(vy, 0.f);
                    *(uint32_t*)(C16 + (size_t)row * HID + col) =
                        pack_h2(__float2half(vx), __float2half(vy));
                } else {
                    *(float2*)(C32 + (size_t)row * HID + col) = make_float2(vx, vy);
                }
            }
        }
    }
}

// ---------------------------------------------------------------------------
// merged CSR count / scan / fill (unchanged)
// ---------------------------------------------------------------------------
__global__ void csr_count(const int* __restrict__ eb, const int* __restrict__ es,
                          const int* __restrict__ em, const int* __restrict__ ein,
                          int* __restrict__ cnt)
{
    int e = blockIdx.x * 256 + threadIdx.x;
    if (e >= ETOT) return;
    const int* dstp; int rowOff, le;
    if      (e <  500000) { dstp = eb + 500000;  rowOff = 0;      le = e; }
    else if (e < 1000000) { dstp = eb;           rowOff = 100000; le = e - 500000; }
    else if (e < 1300000) { dstp = es + 300000;  rowOff = 300000; le = e - 1000000; }
    else if (e < 1600000) { dstp = es;           rowOff = 350000; le = e - 1300000; }
    else if (e < 1900000) { dstp = em + 300000;  rowOff = 550000; le = e - 1600000; }
    else if (e < 2200000) { dstp = em;           rowOff = 650000; le = e - 1900000; }
    else if (e < 2300000) { dstp = ein + 100000; rowOff = 700000; le = e - 2200000; }
    else                  { dstp = ein;          rowOff = 702000; le = e - 2300000; }
    atomicAdd(&cnt[rowOff + dstp[le]], 1);
}

__global__ void scan1_kernel(const int* __restrict__ cnt, int* __restrict__ rowptr,
                             int* __restrict__ bsums, int n)
{
    __shared__ int wsums[8];
    int base = blockIdx.x * 4096 + threadIdx.x * 16;
    int v[16];
    int s = 0;
#pragma unroll
    for (int i = 0; i < 16; i++) {
        v[i] = (base + i < n) ? cnt[base + i] : 0;
        s += v[i];
    }
    int lane = threadIdx.x & 31, w = threadIdx.x >> 5;
    int ps = s;
#pragma unroll
    for (int o = 1; o < 32; o <<= 1) {
        int t = __shfl_up_sync(0xffffffffu, ps, o);
        if (lane >= o) ps += t;
    }
    if (lane == 31) wsums[w] = ps;
    __syncthreads();
    if (w == 0) {
        int t = (lane < 8) ? wsums[lane] : 0;
#pragma unroll
        for (int o = 1; o < 8; o <<= 1) {
            int u = __shfl_up_sync(0xffffffffu, t, o);
            if (lane >= o) t += u;
        }
        if (lane < 8) wsums[lane] = t;
    }
    __syncthreads();
    int excl = ps - s + (w ? wsums[w - 1] : 0);
    int run = excl;
#pragma unroll
    for (int i = 0; i < 16; i++) {
        if (base + i < n) rowptr[base + i] = run;
        run += v[i];
    }
    if (threadIdx.x == 0) bsums[blockIdx.x] = wsums[7];
}

__global__ void scan2_kernel(int* __restrict__ bsums, int nb)
{
    if (threadIdx.x == 0 && blockIdx.x == 0) {
        int run = 0;
        for (int i = 0; i < nb; i++) {
            int t = bsums[i];
            bsums[i] = run;
            run += t;
        }
    }
}

__global__ void scan3_kernel(int* __restrict__ rowptr, const int* __restrict__ bsums,
                             int* __restrict__ cursor, int n)
{
    int base = blockIdx.x * 4096 + threadIdx.x * 16;
    int off = bsums[blockIdx.x];
#pragma unroll
    for (int i = 0; i < 16; i++)
        if (base + i < n) {
            int v = rowptr[base + i] + off;
            rowptr[base + i] = v;
            cursor[base + i] = v;
        }
    if (blockIdx.x == 0 && threadIdx.x == 0) rowptr[n] = ETOT;
}

__global__ void csr_fill(const int* __restrict__ eb, const int* __restrict__ es,
                         const int* __restrict__ em, const int* __restrict__ ein,
                         const float* __restrict__ w0, const float* __restrict__ w1,
                         const float* __restrict__ w2, const float* __restrict__ w3,
                         const float* __restrict__ w4, const float* __restrict__ w5,
                         const float* __restrict__ w6, const float* __restrict__ w7,
                         int* __restrict__ cursor, int* __restrict__ srcg,
                         float* __restrict__ wg)
{
    int e = blockIdx.x * 256 + threadIdx.x;
    if (e >= ETOT) return;
    const int *dstp, *srcp; const float* ewp; int rowOff, le;
    if      (e <  500000) { dstp = eb + 500000;  srcp = eb;           ewp = w0; rowOff = 0;      le = e; }
    else if (e < 1000000) { dstp = eb;           srcp = eb + 500000;  ewp = w1; rowOff = 100000; le = e - 500000; }
    else if (e < 1300000) { dstp = es + 300000;  srcp = es;           ewp = w2; rowOff = 300000; le = e - 1000000; }
    else if (e < 1600000) { dstp = es;           srcp = es + 300000;  ewp = w3; rowOff = 350000; le = e - 1300000; }
    else if (e < 1900000) { dstp = em + 300000;  srcp = em;           ewp = w4; rowOff = 550000; le = e - 1600000; }
    else if (e < 2200000) { dstp = em;           srcp = em + 300000;  ewp = w5; rowOff = 650000; le = e - 1900000; }
    else if (e < 2300000) { dstp = ein + 100000; srcp = ein;          ewp = w6; rowOff = 700000; le = e - 2200000; }
    else                  { dstp = ein;          srcp = ein + 100000; ewp = w7; rowOff = 702000; le = e - 2300000; }
    int slot = atomicAdd(&cursor[rowOff + dstp[le]], 1);
    srcg[slot] = srcp[le];
    wg[slot]   = ewp[le];
}

// ---------------------------------------------------------------------------
// weights / bias / conversions (unchanged)
// ---------------------------------------------------------------------------
__global__ void wsum_kernel(const float* __restrict__ W1l, const float* __restrict__ b1,
                            const float* __restrict__ W2l, const float* __restrict__ b2,
                            float* __restrict__ wsum, float* __restrict__ bsum)
{
    const int dstT[8] = {1, 0, 3, 0, 1, 3, 2, 1};
    int idx = blockIdx.x * blockDim.x + threadIdx.x;
    if (idx >= 2 * 4 * HID * HID) return;
    int l  = idx / (4 * HID * HID);
    int r  = idx % (4 * HID * HID);
    int d  = r / (HID * HID);
    int ij = r % (HID * HID);
    const float* W = l ? W2l : W1l;
    float s = 0.f;
#pragma unroll
    for (int t = 0; t < 8; t++)
        if (dstT[t] == d) s += W[t * HID * HID + ij];
    wsum[idx] = s;
    if (ij < HID) {
        const float* B = l ? b2 : b1;
        float sb = 0.f;
#pragma unroll
        for (int t = 0; t < 8; t++)
            if (dstT[t] == d) sb += B[t * HID + ij];
        bsum[(l * 4 + d) * HID + ij] = sb;
    }
}

__global__ void wsplit_kernel(const float* __restrict__ wsum,
                              const float* __restrict__ W1r,
                              const float* __restrict__ W2r,
                              __half* __restrict__ wh, __half* __restrict__ wl)
{
    int idx = blockIdx.x * blockDim.x + threadIdx.x;
    if (idx >= NWCHUNK * HID * HID) return;
    int c  = idx >> 14;
    int ij = idx & 16383;
    float v = (c < 8) ? wsum[idx]
            : (c < 16) ? W1r[(c - 8) * HID * HID + ij]
                       : W2r[(c - 16) * HID * HID + ij];
    __half h = __float2half(v);
    wh[idx] = h;
    wl[idx] = __float2half(v - __half2float(h));
}

__global__ void xhalf_kernel(const float* __restrict__ xu, const float* __restrict__ xp,
                             const float* __restrict__ xc, const float* __restrict__ xq,
                             __half* __restrict__ x16)
{
    int i = blockIdx.x * 256 + threadIdx.x;
    if (i >= NTOT * 16) return;
    int row = i >> 4;
    int c8  = (i & 15) << 3;
    const float* x;
    int lrow;
    if      (row < NU)           { x = xu; lrow = row; }
    else if (row < NU + NP)      { x = xp; lrow = row - NU; }
    else if (row < NU + NP + NC) { x = xc; lrow = row - NU - NP; }
    else                         { x = xq; lrow = row - NU - NP - NC; }
    float4 v0 = *(const float4*)(x + (size_t)lrow * HID + c8);
    float4 v1 = *(const float4*)(x + (size_t)lrow * HID + c8 + 4);
    uint4 o;
    o.x = pack_h2(__float2half(v0.x), __float2half(v0.y));
    o.y = pack_h2(__float2half(v0.z), __float2half(v0.w));
    o.z = pack_h2(__float2half(v1.x), __float2half(v1.y));
    o.w = pack_h2(__float2half(v1.z), __float2half(v1.w));
    *(uint4*)(x16 + (size_t)row * HID + c8) = o;
}

// ---------------------------------------------------------------------------
// CSR gather: TWO rows per warp, 16 lanes/row, uint4 (16B) lane loads.
// fp16 source, fp32 accumulate, fp16 aggr out. 2-edge unroll.
// ---------------------------------------------------------------------------
__global__ void gather_kernel(const __half* __restrict__ xbase,
                              const int* __restrict__ rowptr,
                              const int* __restrict__ srcg,
                              const float* __restrict__ wg,
                              __half* __restrict__ a16)
{
    int gw   = (blockIdx.x * blockDim.x + threadIdx.x) >> 5;
    int lane = threadIdx.x & 31;
    int row  = gw * 2 + (lane >> 4);
    int l16  = lane & 15;
    if (row >= NROWS) return;
    const size_t OU = 0, OP = (size_t)NU * HID, OC = (size_t)(NU + NP) * HID,
                 OQ = (size_t)(NU + NP + NC) * HID;
    size_t xo = (row <  100000) ? OU
              : (row <  300000) ? OP
              : (row <  350000) ? OU
              : (row <  550000) ? OQ
              : (row <  650000) ? OQ
              : (row <  702000) ? OP : OC;
    const __half* x = xbase + xo;

    int e0 = rowptr[row], e1 = rowptr[row + 1];
    float acc[8] = {0.f, 0.f, 0.f, 0.f, 0.f, 0.f, 0.f, 0.f};
    int e = e0;
    for (; e + 1 < e1; e += 2) {
        int   s0 = srcg[e],  s1 = srcg[e + 1];
        float w0 = wg[e],    w1 = wg[e + 1];
        uint4 u0 = *((const uint4*)(x + (size_t)s0 * HID) + l16);
        uint4 u1 = *((const uint4*)(x + (size_t)s1 * HID) + l16);
        const uint32_t* q0 = &u0.x;
        const uint32_t* q1 = &u1.x;
#pragma unroll
        for (int k = 0; k < 4; k++) {
            float2 f0 = __half22float2(*reinterpret_cast<const __half2*>(&q0[k]));
            float2 f1 = __half22float2(*reinterpret_cast<const __half2*>(&q1[k]));
            acc[2 * k + 0] += w0 * f0.x + w1 * f1.x;
            acc[2 * k + 1] += w0 * f0.y + w1 * f1.y;
        }
    }
    if (e < e1) {
        int s0 = srcg[e];
        float w0 = wg[e];
        uint4 u0 = *((const uint4*)(x + (size_t)s0 * HID) + l16);
        const uint32_t* q0 = &u0.x;
#pragma unroll
        for (int k = 0; k < 4; k++) {
            float2 f0 = __half22float2(*reinterpret_cast<const __half2*>(&q0[k]));
            acc[2 * k + 0] += w0 * f0.x;
            acc[2 * k + 1] += w0 * f0.y;
        }
    }
    float invd = 1.f / fmaxf((float)(e1 - e0), 1.f);
    uint4 o;
    uint32_t* oq = &o.x;
#pragma unroll
    for (int k = 0; k < 4; k++)
        oq[k] = pack_h2(__float2half(acc[2 * k] * invd),
                        __float2half(acc[2 * k + 1] * invd));
    *((uint4*)(a16 + (size_t)row * HID) + l16) = o;
}

// ---------------------------------------------------------------------------
// Host launch — fork/join streams for prep||CSR and the 4 per-dst GEMMs.
// ---------------------------------------------------------------------------
extern "C" void kernel_launch(void* const* d_in, const int* in_sizes, int n_in,
                              void* d_out, int out_size)
{
    (void)in_sizes; (void)n_in; (void)out_size;

    static const int rowOffR[8] = {0, 100000, 300000, 350000, 550000, 650000, 700000, 702000};
    static const int relForDst[4][3] = { {1, 3, -1}, {0, 4, 7}, {6, -1, -1}, {2, 5, -1} };
    static const int nRelForDst[4]   = { 2, 3, 1, 2 };
    static const int    nodeN[4]   = {NU, NP, NC, NQ};
    static const size_t nodeOff[4] = {0, NU, NU + NP, NU + NP + NC};

    static cudaStream_t sx[3] = {0, 0, 0};
    static cudaEvent_t  ev[12];
    static int inited = 0;
    if (!inited) {
        for (int i = 0; i < 3; i++)
            cudaStreamCreateWithFlags(&sx[i], cudaStreamNonBlocking);
        for (int i = 0; i < 12; i++)
            cudaEventCreateWithFlags(&ev[i], cudaEventDisableTiming);
        cudaFuncSetAttribute(gemm_mma<2,0>, cudaFuncAttributeMaxDynamicSharedMemorySize, SMEM_BYTES);
        cudaFuncSetAttribute(gemm_mma<3,0>, cudaFuncAttributeMaxDynamicSharedMemorySize, SMEM_BYTES);
        cudaFuncSetAttribute(gemm_mma<4,0>, cudaFuncAttributeMaxDynamicSharedMemorySize, SMEM_BYTES);
        cudaFuncSetAttribute(gemm_mma<2,1>, cudaFuncAttributeMaxDynamicSharedMemorySize, SMEM_BYTES);
        cudaFuncSetAttribute(gemm_mma<3,1>, cudaFuncAttributeMaxDynamicSharedMemorySize, SMEM_BYTES);
        cudaFuncSetAttribute(gemm_mma<4,1>, cudaFuncAttributeMaxDynamicSharedMemorySize, SMEM_BYTES);
        inited = 1;
    }

    float *wsum, *bsum, *wg;
    __half *x16, *h16, *a16, *wh, *wl;
    int *cnt, *rowptr, *cursor, *srcg, *bsums;
    cudaGetSymbolAddress((void**)&x16,    g_x16);
    cudaGetSymbolAddress((void**)&h16,    g_h16);
    cudaGetSymbolAddress((void**)&a16,    g_a16);
    cudaGetSymbolAddress((void**)&cnt,    g_cnt);
    cudaGetSymbolAddress((void**)&rowptr, g_rowptr);
    cudaGetSymbolAddress((void**)&cursor, g_cursor);
    cudaGetSymbolAddress((void**)&srcg,   g_srcg);
    cudaGetSymbolAddress((void**)&wg,     g_wg);
    cudaGetSymbolAddress((void**)&bsums,  g_bsums);
    cudaGetSymbolAddress((void**)&wsum,   g_wsum);
    cudaGetSymbolAddress((void**)&bsum,   g_bsum);
    cudaGetSymbolAddress((void**)&wh,     g_wh);
    cudaGetSymbolAddress((void**)&wl,     g_wl);

    const float* xu = (const float*)d_in[0];
    const float* xp = (const float*)d_in[1];
    const float* xc = (const float*)d_in[2];
    const float* xq = (const float*)d_in[3];
    const float* W1l = (const float*)d_in[4];
    const float* b1  = (const float*)d_in[5];
    const float* W1r = (const float*)d_in[6];
    const float* W2l = (const float*)d_in[7];
    const float* b2  = (const float*)d_in[8];
    const float* W2r = (const float*)d_in[9];
    const int* eb  = (const int*)d_in[18];
    const int* es  = (const int*)d_in[19];
    const int* em  = (const int*)d_in[20];
    const int* ein = (const int*)d_in[21];
    float* out = (float*)d_out;

    cudaStream_t st = 0;
    const int NSCAN = (NROWS + 4095) / 4096;

    // ---- fork: prep chain on sx[0], CSR chain on st ----
    cudaEventRecord(ev[0], st);
    cudaStreamWaitEvent(sx[0], ev[0], 0);
    wsum_kernel<<<(2 * 4 * HID * HID + 255) / 256, 256, 0, sx[0]>>>(W1l, b1, W2l, b2, wsum, bsum);
    wsplit_kernel<<<(NWCHUNK * HID * HID + 255) / 256, 256, 0, sx[0]>>>(wsum, W1r, W2r, wh, wl);
    xhalf_kernel<<<(NTOT * 16 + 255) / 256, 256, 0, sx[0]>>>(xu, xp, xc, xq, x16);
    cudaEventRecord(ev[1], sx[0]);

    cudaMemsetAsync(cnt, 0, NROWS * sizeof(int), st);
    csr_count<<<(ETOT + 255) / 256, 256, 0, st>>>(eb, es, em, ein, cnt);
    scan1_kernel<<<NSCAN, 256, 0, st>>>(cnt, rowptr, bsums, NROWS);
    scan2_kernel<<<1, 32, 0, st>>>(bsums, NSCAN);
    scan3_kernel<<<NSCAN, 256, 0, st>>>(rowptr, bsums, cursor, NROWS);
    csr_fill<<<(ETOT + 255) / 256, 256, 0, st>>>(
        eb, es, em, ein,
        (const float*)d_in[10], (const float*)d_in[11], (const float*)d_in[12],
        (const float*)d_in[13], (const float*)d_in[14], (const float*)d_in[15],
        (const float*)d_in[16], (const float*)d_in[17],
        cursor, srcg, wg);
    cudaStreamWaitEvent(st, ev[1], 0);   // join: st now has CSR + prep done

    // ---- two layers ----
    for (int layer = 0; layer < 2; layer++) {
        const __half* src = layer ? h16 : x16;
        gather_kernel<<<((NROWS + 1) / 2 * 32 + 255) / 256, 256, 0, st>>>(
            src, rowptr, srcg, wg, a16);

        // fork GEMMs: d=1 (product, largest) on st; others on sx[0..2]
        int eb_ = 2 + layer * 5;
        cudaEventRecord(ev[eb_], st);
        for (int k = 0; k < 3; k++) cudaStreamWaitEvent(sx[k], ev[eb_], 0);

        static const int dOrder[4] = {1, 0, 3, 2};
        for (int q = 0; q < 4; q++) {
            int d = dOrder[q];
            cudaStream_t gs = (q == 0) ? st : sx[q - 1];

            const __half *Ap[3]  = {nullptr, nullptr, nullptr};
            const __half *Whp[4] = {nullptr, nullptr, nullptr, nullptr};
            const __half *Wlp[4] = {nullptr, nullptr, nullptr, nullptr};
            Whp[0] = wh + (size_t)(layer * 4 + d) * HID * HID;
            Wlp[0] = wl + (size_t)(layer * 4 + d) * HID * HID;
            for (int r = 0; r < nRelForDst[d]; r++) {
                int t = relForDst[d][r];
                Ap[r] = a16 + (size_t)rowOffR[t] * HID;
                Whp[r + 1] = wh + (size_t)(8 + layer * 8 + t) * HID * HID;
                Wlp[r + 1] = wl + (size_t)(8 + layer * 8 + t) * HID * HID;
            }
            GemmArgs p;
            p.A0 = src + nodeOff[d] * HID;
            p.A1 = Ap[0]; p.A2 = Ap[1]; p.A3 = Ap[2];
            p.W0h = Whp[0]; p.W0l = Wlp[0];
            p.W1h = Whp[1]; p.W1l = Wlp[1];
            p.W2h = Whp[2]; p.W2l = Wlp[2];
            p.W3h = Whp[3]; p.W3l = Wlp[3];
            int nch = 1 + nRelForDst[d];
            float* C32 = layer ? (out + nodeOff[d] * HID) : nullptr;
            __half* C16 = layer ? nullptr : (h16 + nodeOff[d] * HID);
            const float* bs = bsum + (layer * 4 + d) * HID;
            int grid = (nodeN[d] + 127) / 128;
            if (layer == 0) {
                if (nch == 2)      gemm_mma<2,1><<<grid, 256, SMEM_BYTES, gs>>>(p, bs, C32, C16, nodeN[d]);
                else if (nch == 3) gemm_mma<3,1><<<grid, 256, SMEM_BYTES, gs>>>(p, bs, C32, C16, nodeN[d]);
                else               gemm_mma<4,1><<<grid, 256, SMEM_BYTES, gs>>>(p, bs, C32, C16, nodeN[d]);
            } else {
                if (nch == 2)      gemm_mma<2,0><<<grid, 256, SMEM_BYTES, gs>>>(p, bs, C32, C16, nodeN[d]);
                else if (nch == 3) gemm_mma<3,0><<<grid, 256, SMEM_BYTES, gs>>>(p, bs, C32, C16, nodeN[d]);
                else               gemm_mma<4,0><<<grid, 256, SMEM_BYTES, gs>>>(p, bs, C32, C16, nodeN[d]);
            }
        }
        // join back to st
        for (int k = 0; k < 3; k++) {
            cudaEventRecord(ev[eb_ + 1 + k], sx[k]);
            cudaStreamWaitEvent(st, ev[eb_ + 1 + k], 0);
        }
    }
}

// round 17
// speedup vs baseline: 1.8408x; 1.2110x over previous
#include <cuda_runtime.h>
#include <cuda_fp16.h>
#include <stdint.h>

// ---------------------------------------------------------------------------
// HeteroGraphSAGE, 2 layers, 4 node types, 8 relations.  fp16 data plane:
// x0/h/aggr stored fp16 (node tables L2-resident for random gathers).
// GEMM = fp16 x fp16 SINGLE pass (R17: with the cp.async pipeline hiding
// fills, the mainloop is MMA/LDSM-issue bound -> halving passes now pays;
// R14's failure was under the fill-bound regime). Double-buffered cp.async,
// occupancy 2. Gather: 2 rows/warp, uint4 lane loads. Streams overlap
// prep||CSR and the 4 per-dst GEMMs.
// ---------------------------------------------------------------------------

#define NU 200000
#define NP 100000
#define NC 2000
#define NQ 50000
#define NTOT 352000
#define HID 128

#define NROWS 802000
#define ETOT  2400000
#define NWCHUNK 24

#define LDS 72
#define LDSB 144
#define TILE_B (128 * LDSB)          // 18432 B
#define STAGE_B (2 * TILE_B)         // A, W = 36864 B
#define SMEM_BYTES (2 * STAGE_B)     // double buffer = 73728 B (occ 2)

// device globals (allocation-free scratch)
__device__ __half g_x16[(size_t)NTOT * HID];
__device__ __half g_h16[(size_t)NTOT * HID];
__device__ __half g_a16[(size_t)NROWS * HID];
__device__ int    g_cnt[NROWS];
__device__ int    g_rowptr[NROWS + 1];
__device__ int    g_cursor[NROWS];
__device__ int    g_srcg[ETOT];
__device__ float  g_wg[ETOT];
__device__ int    g_bsums[512];
__device__ float  g_wsum[2 * 4 * HID * HID];
__device__ float  g_bsum[2 * 4 * HID];
__device__ __half g_w16[NWCHUNK * HID * HID];

// ---------------------------------------------------------------------------
// PTX helpers
// ---------------------------------------------------------------------------
#define LDSM4(R, addr)                                                          \
    asm volatile("ldmatrix.sync.aligned.m8n8.x4.shared.b16 {%0,%1,%2,%3}, [%4];" \
                 : "=r"((R)[0]), "=r"((R)[1]), "=r"((R)[2]), "=r"((R)[3])        \
                 : "r"(addr))

#define MMAF16(C, A, B0, B1)                                                    \
    asm volatile("mma.sync.aligned.m16n8k16.row.col.f32.f16.f16.f32 "           \
                 "{%0,%1,%2,%3},{%4,%5,%6,%7},{%8,%9},{%0,%1,%2,%3};"           \
                 : "+f"((C)[0]), "+f"((C)[1]), "+f"((C)[2]), "+f"((C)[3])        \
                 : "r"((A)[0]), "r"((A)[1]), "r"((A)[2]), "r"((A)[3]),           \
                   "r"(B0), "r"(B1))

__device__ __forceinline__ void cpa16(uint32_t dst, const void* src, uint32_t sz)
{
    asm volatile("cp.async.cg.shared.global [%0], [%1], 16, %2;"
                 :: "r"(dst), "l"(src), "r"(sz) : "memory");
}

__device__ __forceinline__ uint32_t pack_h2(__half a, __half b)
{
    __half2 p = __halves2half2(a, b);
    return *reinterpret_cast<uint32_t*>(&p);
}

// ---------------------------------------------------------------------------
// Multi-chunk fp16 tensor-core GEMM (single pass), double-buffered cp.async:
//   C = bias + sum_ch A_ch @ W_ch^T
// NCH = chunks. L0=1: relu + write fp16 h; L0=0: write fp32 out.
// Block tile 128x128, 8 warps (4m x 2n), occ 2.
// ---------------------------------------------------------------------------
struct GemmArgs {
    const __half *A0, *A1, *A2, *A3;
    const __half *W0, *W1, *W2, *W3;
};

__device__ __forceinline__ void issue_stage(const GemmArgs& p, int s, uint32_t bufb,
                                            int bm, int n, int tid)
{
    int ch = s >> 1;
    const __half* A = (ch == 0) ? p.A0 : (ch == 1) ? p.A1 : (ch == 2) ? p.A2 : p.A3;
    const __half* W = (ch == 0) ? p.W0 : (ch == 1) ? p.W1 : (ch == 2) ? p.W2 : p.W3;
    int kb = (s & 1) * 64;

#pragma unroll
    for (int it = 0; it < 4; it++) {
        int idx = tid + it * 256;
        int r   = idx >> 3;
        int kc  = (idx & 7) << 3;
        int grow = bm + r;
        int rowc = (grow < n) ? grow : (n - 1);
        uint32_t ok = (grow < n) ? 16u : 0u;
        size_t ga = (size_t)rowc * HID + kb + kc;
        size_t gw = (size_t)r * HID + kb + kc;
        uint32_t so = r * LDSB + kc * 2;
        cpa16(bufb + so,          A + ga, ok);
        cpa16(bufb + TILE_B + so, W + gw, 16u);
    }
    asm volatile("cp.async.commit_group;" ::: "memory");
}

template <int NCH, int L0>
__global__ void __launch_bounds__(256, 2)
gemm_mma(GemmArgs p, const float* __restrict__ bias,
         float* __restrict__ C32, __half* __restrict__ C16, int n)
{
    extern __shared__ __half smem[];
    uint32_t sb = (uint32_t)__cvta_generic_to_shared(smem);

    const int tid  = threadIdx.x;
    const int lane = tid & 31;
    const int warp = tid >> 5;
    const int wm = warp >> 1;
    const int wn = warp & 1;
    const int bm = blockIdx.x * 128;

    float c[2][8][4];
#pragma unroll
    for (int i = 0; i < 2; i++)
#pragma unroll
        for (int j = 0; j < 8; j++)
#pragma unroll
            for (int q = 0; q < 4; q++) c[i][j][q] = 0.f;

    const int nst = NCH * 2;

    issue_stage(p, 0, sb, bm, n, tid);
    issue_stage(p, 1, sb + STAGE_B, bm, n, tid);

    for (int s = 0; s < nst; s++) {
        if (s + 1 < nst)
            asm volatile("cp.async.wait_group 1;" ::: "memory");
        else
            asm volatile("cp.async.wait_group 0;" ::: "memory");
        __syncthreads();

        uint32_t bufb = sb + (s & 1) * STAGE_B;

#pragma unroll
        for (int ks = 0; ks < 4; ks++) {
            uint32_t a[2][4], b[4][4];
#pragma unroll
            for (int i = 0; i < 2; i++) {
                int r   = wm * 32 + i * 16 + (lane & 15);
                int kby = ks * 32 + ((lane >> 4) << 4);
                LDSM4(a[i], bufb + r * LDSB + kby);
            }
#pragma unroll
            for (int pq = 0; pq < 4; pq++) {
                int nr  = wn * 64 + (2 * pq + (lane >> 4)) * 8 + (lane & 7);
                int kby = ks * 32 + ((lane >> 3) & 1) * 16;
                LDSM4(b[pq], bufb + TILE_B + nr * LDSB + kby);
            }
#pragma unroll
            for (int i = 0; i < 2; i++)
#pragma unroll
                for (int j = 0; j < 8; j++) {
                    const uint32_t* bb = b[j >> 1] + (j & 1) * 2;
                    MMAF16(c[i][j], a[i], bb[0], bb[1]);
                }
        }
        __syncthreads();
        if (s + 2 < nst)
            issue_stage(p, s + 2, sb + (s & 1) * STAGE_B, bm, n, tid);
    }

    // ---- epilogue ----
    const int g  = lane >> 2;
    const int tq = lane & 3;
#pragma unroll
    for (int i = 0; i < 2; i++) {
#pragma unroll
        for (int half = 0; half < 2; half++) {
            int row = bm + wm * 32 + i * 16 + half * 8 + g;
            if (row >= n) continue;
#pragma unroll
            for (int j = 0; j < 8; j++) {
                int col = wn * 64 + j * 8 + tq * 2;
                float vx = c[i][j][half * 2 + 0] + bias[col];
                float vy = c[i][j][half * 2 + 1] + bias[col + 1];
                if (L0) {
                    vx = fmaxf(vx, 0.f);
                    vy = fmaxf(vy, 0.f);
                    *(uint32_t*)(C16 + (size_t)row * HID + col) =
                        pack_h2(__float2half(vx), __float2half(vy));
                } else {
                    *(float2*)(C32 + (size_t)row * HID + col) = make_float2(vx, vy);
                }
            }
        }
    }
}

// ---------------------------------------------------------------------------
// merged CSR count / scan / fill
// ---------------------------------------------------------------------------
__global__ void csr_count(const int* __restrict__ eb, const int* __restrict__ es,
                          const int* __restrict__ em, const int* __restrict__ ein,
                          int* __restrict__ cnt)
{
    int e = blockIdx.x * 256 + threadIdx.x;
    if (e >= ETOT) return;
    const int* dstp; int rowOff, le;
    if      (e <  500000) { dstp = eb + 500000;  rowOff = 0;      le = e; }
    else if (e < 1000000) { dstp = eb;           rowOff = 100000; le = e - 500000; }
    else if (e < 1300000) { dstp = es + 300000;  rowOff = 300000; le = e - 1000000; }
    else if (e < 1600000) { dstp = es;           rowOff = 350000; le = e - 1300000; }
    else if (e < 1900000) { dstp = em + 300000;  rowOff = 550000; le = e - 1600000; }
    else if (e < 2200000) { dstp = em;           rowOff = 650000; le = e - 1900000; }
    else if (e < 2300000) { dstp = ein + 100000; rowOff = 700000; le = e - 2200000; }
    else                  { dstp = ein;          rowOff = 702000; le = e - 2300000; }
    atomicAdd(&cnt[rowOff + dstp[le]], 1);
}

__global__ void scan1_kernel(const int* __restrict__ cnt, int* __restrict__ rowptr,
                             int* __restrict__ bsums, int n)
{
    __shared__ int wsums[8];
    int base = blockIdx.x * 4096 + threadIdx.x * 16;
    int v[16];
    int s = 0;
#pragma unroll
    for (int i = 0; i < 16; i++) {
        v[i] = (base + i < n) ? cnt[base + i] : 0;
        s += v[i];
    }
    int lane = threadIdx.x & 31, w = threadIdx.x >> 5;
    int ps = s;
#pragma unroll
    for (int o = 1; o < 32; o <<= 1) {
        int t = __shfl_up_sync(0xffffffffu, ps, o);
        if (lane >= o) ps += t;
    }
    if (lane == 31) wsums[w] = ps;
    __syncthreads();
    if (w == 0) {
        int t = (lane < 8) ? wsums[lane] : 0;
#pragma unroll
        for (int o = 1; o < 8; o <<= 1) {
            int u = __shfl_up_sync(0xffffffffu, t, o);
            if (lane >= o) t += u;
        }
        if (lane < 8) wsums[lane] = t;
    }
    __syncthreads();
    int excl = ps - s + (w ? wsums[w - 1] : 0);
    int run = excl;
#pragma unroll
    for (int i = 0; i < 16; i++) {
        if (base + i < n) rowptr[base + i] = run;
        run += v[i];
    }
    if (threadIdx.x == 0) bsums[blockIdx.x] = wsums[7];
}

__global__ void scan2_kernel(int* __restrict__ bsums, int nb)
{
    if (threadIdx.x == 0 && blockIdx.x == 0) {
        int run = 0;
        for (int i = 0; i < nb; i++) {
            int t = bsums[i];
            bsums[i] = run;
            run += t;
        }
    }
}

__global__ void scan3_kernel(int* __restrict__ rowptr, const int* __restrict__ bsums,
                             int* __restrict__ cursor, int n)
{
    int base = blockIdx.x * 4096 + threadIdx.x * 16;
    int off = bsums[blockIdx.x];
#pragma unroll
    for (int i = 0; i < 16; i++)
        if (base + i < n) {
            int v = rowptr[base + i] + off;
            rowptr[base + i] = v;
            cursor[base + i] = v;
        }
    if (blockIdx.x == 0 && threadIdx.x == 0) rowptr[n] = ETOT;
}

__global__ void csr_fill(const int* __restrict__ eb, const int* __restrict__ es,
                         const int* __restrict__ em, const int* __restrict__ ein,
                         const float* __restrict__ w0, const float* __restrict__ w1,
                         const float* __restrict__ w2, const float* __restrict__ w3,
                         const float* __restrict__ w4, const float* __restrict__ w5,
                         const float* __restrict__ w6, const float* __restrict__ w7,
                         int* __restrict__ cursor, int* __restrict__ srcg,
                         float* __restrict__ wg)
{
    int e = blockIdx.x * 256 + threadIdx.x;
    if (e >= ETOT) return;
    const int *dstp, *srcp; const float* ewp; int rowOff, le;
    if      (e <  500000) { dstp = eb + 500000;  srcp = eb;           ewp = w0; rowOff = 0;      le = e; }
    else if (e < 1000000) { dstp = eb;           srcp = eb + 500000;  ewp = w1; rowOff = 100000; le = e - 500000; }
    else if (e < 1300000) { dstp = es + 300000;  srcp = es;           ewp = w2; rowOff = 300000; le = e - 1000000; }
    else if (e < 1600000) { dstp = es;           srcp = es + 300000;  ewp = w3; rowOff = 350000; le = e - 1300000; }
    else if (e < 1900000) { dstp = em + 300000;  srcp = em;           ewp = w4; rowOff = 550000; le = e - 1600000; }
    else if (e < 2200000) { dstp = em;           srcp = em + 300000;  ewp = w5; rowOff = 650000; le = e - 1900000; }
    else if (e < 2300000) { dstp = ein + 100000; srcp = ein;          ewp = w6; rowOff = 700000; le = e - 2200000; }
    else                  { dstp = ein;          srcp = ein + 100000; ewp = w7; rowOff = 702000; le = e - 2300000; }
    int slot = atomicAdd(&cursor[rowOff + dstp[le]], 1);
    srcg[slot] = srcp[le];
    wg[slot]   = ewp[le];
}

// ---------------------------------------------------------------------------
// weights / bias / conversions
// ---------------------------------------------------------------------------
__global__ void wsum_kernel(const float* __restrict__ W1l, const float* __restrict__ b1,
                            const float* __restrict__ W2l, const float* __restrict__ b2,
                            float* __restrict__ wsum, float* __restrict__ bsum)
{
    const int dstT[8] = {1, 0, 3, 0, 1, 3, 2, 1};
    int idx = blockIdx.x * blockDim.x + threadIdx.x;
    if (idx >= 2 * 4 * HID * HID) return;
    int l  = idx / (4 * HID * HID);
    int r  = idx % (4 * HID * HID);
    int d  = r / (HID * HID);
    int ij = r % (HID * HID);
    const float* W = l ? W2l : W1l;
    float s = 0.f;
#pragma unroll
    for (int t = 0; t < 8; t++)
        if (dstT[t] == d) s += W[t * HID * HID + ij];
    wsum[idx] = s;
    if (ij < HID) {
        const float* B = l ? b2 : b1;
        float sb = 0.f;
#pragma unroll
        for (int t = 0; t < 8; t++)
            if (dstT[t] == d) sb += B[t * HID + ij];
        bsum[(l * 4 + d) * HID + ij] = sb;
    }
}

__global__ void wconv_kernel(const float* __restrict__ wsum,
                             const float* __restrict__ W1r,
                             const float* __restrict__ W2r,
                             __half* __restrict__ w16)
{
    int idx = blockIdx.x * blockDim.x + threadIdx.x;
    if (idx >= NWCHUNK * HID * HID) return;
    int c  = idx >> 14;
    int ij = idx & 16383;
    float v = (c < 8) ? wsum[idx]
            : (c < 16) ? W1r[(c - 8) * HID * HID + ij]
                       : W2r[(c - 16) * HID * HID + ij];
    w16[idx] = __float2half(v);
}

__global__ void xhalf_kernel(const float* __restrict__ xu, const float* __restrict__ xp,
                             const float* __restrict__ xc, const float* __restrict__ xq,
                             __half* __restrict__ x16)
{
    int i = blockIdx.x * 256 + threadIdx.x;
    if (i >= NTOT * 16) return;
    int row = i >> 4;
    int c8  = (i & 15) << 3;
    const float* x;
    int lrow;
    if      (row < NU)           { x = xu; lrow = row; }
    else if (row < NU + NP)      { x = xp; lrow = row - NU; }
    else if (row < NU + NP + NC) { x = xc; lrow = row - NU - NP; }
    else                         { x = xq; lrow = row - NU - NP - NC; }
    float4 v0 = *(const float4*)(x + (size_t)lrow * HID + c8);
    float4 v1 = *(const float4*)(x + (size_t)lrow * HID + c8 + 4);
    uint4 o;
    o.x = pack_h2(__float2half(v0.x), __float2half(v0.y));
    o.y = pack_h2(__float2half(v0.z), __float2half(v0.w));
    o.z = pack_h2(__float2half(v1.x), __float2half(v1.y));
    o.w = pack_h2(__float2half(v1.z), __float2half(v1.w));
    *(uint4*)(x16 + (size_t)row * HID + c8) = o;
}

// ---------------------------------------------------------------------------
// CSR gather: TWO rows per warp, 16 lanes/row, uint4 lane loads.
// ---------------------------------------------------------------------------
__global__ void gather_kernel(const __half* __restrict__ xbase,
                              const int* __restrict__ rowptr,
                              const int* __restrict__ srcg,
                              const float* __restrict__ wg,
                              __half* __restrict__ a16)
{
    int gw   = (blockIdx.x * blockDim.x + threadIdx.x) >> 5;
    int lane = threadIdx.x & 31;
    int row  = gw * 2 + (lane >> 4);
    int l16  = lane & 15;
    if (row >= NROWS) return;
    const size_t OU = 0, OP = (size_t)NU * HID, OC = (size_t)(NU + NP) * HID,
                 OQ = (size_t)(NU + NP + NC) * HID;
    size_t xo = (row <  100000) ? OU
              : (row <  300000) ? OP
              : (row <  350000) ? OU
              : (row <  550000) ? OQ
              : (row <  650000) ? OQ
              : (row <  702000) ? OP : OC;
    const __half* x = xbase + xo;

    int e0 = rowptr[row], e1 = rowptr[row + 1];
    float acc[8] = {0.f, 0.f, 0.f, 0.f, 0.f, 0.f, 0.f, 0.f};
    int e = e0;
    for (; e + 1 < e1; e += 2) {
        int   s0 = srcg[e],  s1 = srcg[e + 1];
        float w0 = wg[e],    w1 = wg[e + 1];
        uint4 u0 = *((const uint4*)(x + (size_t)s0 * HID) + l16);
        uint4 u1 = *((const uint4*)(x + (size_t)s1 * HID) + l16);
        const uint32_t* q0 = &u0.x;
        const uint32_t* q1 = &u1.x;
#pragma unroll
        for (int k = 0; k < 4; k++) {
            float2 f0 = __half22float2(*reinterpret_cast<const __half2*>(&q0[k]));
            float2 f1 = __half22float2(*reinterpret_cast<const __half2*>(&q1[k]));
            acc[2 * k + 0] += w0 * f0.x + w1 * f1.x;
            acc[2 * k + 1] += w0 * f0.y + w1 * f1.y;
        }
    }
    if (e < e1) {
        int s0 = srcg[e];
        float w0 = wg[e];
        uint4 u0 = *((const uint4*)(x + (size_t)s0 * HID) + l16);
        const uint32_t* q0 = &u0.x;
#pragma unroll
        for (int k = 0; k < 4; k++) {
            float2 f0 = __half22float2(*reinterpret_cast<const __half2*>(&q0[k]));
            acc[2 * k + 0] += w0 * f0.x;
            acc[2 * k + 1] += w0 * f0.y;
        }
    }
    float invd = 1.f / fmaxf((float)(e1 - e0), 1.f);
    uint4 o;
    uint32_t* oq = &o.x;
#pragma unroll
    for (int k = 0; k < 4; k++)
        oq[k] = pack_h2(__float2half(acc[2 * k] * invd),
                        __float2half(acc[2 * k + 1] * invd));
    *((uint4*)(a16 + (size_t)row * HID) + l16) = o;
}

// ---------------------------------------------------------------------------
// Host launch — fork/join streams for prep||CSR and the 4 per-dst GEMMs.
// ---------------------------------------------------------------------------
extern "C" void kernel_launch(void* const* d_in, const int* in_sizes, int n_in,
                              void* d_out, int out_size)
{
    (void)in_sizes; (void)n_in; (void)out_size;

    static const int rowOffR[8] = {0, 100000, 300000, 350000, 550000, 650000, 700000, 702000};
    static const int relForDst[4][3] = { {1, 3, -1}, {0, 4, 7}, {6, -1, -1}, {2, 5, -1} };
    static const int nRelForDst[4]   = { 2, 3, 1, 2 };
    static const int    nodeN[4]   = {NU, NP, NC, NQ};
    static const size_t nodeOff[4] = {0, NU, NU + NP, NU + NP + NC};

    static cudaStream_t sx[3] = {0, 0, 0};
    static cudaEvent_t  ev[12];
    static int inited = 0;
    if (!inited) {
        for (int i = 0; i < 3; i++)
            cudaStreamCreateWithFlags(&sx[i], cudaStreamNonBlocking);
        for (int i = 0; i < 12; i++)
            cudaEventCreateWithFlags(&ev[i], cudaEventDisableTiming);
        cudaFuncSetAttribute(gemm_mma<2,0>, cudaFuncAttributeMaxDynamicSharedMemorySize, SMEM_BYTES);
        cudaFuncSetAttribute(gemm_mma<3,0>, cudaFuncAttributeMaxDynamicSharedMemorySize, SMEM_BYTES);
        cudaFuncSetAttribute(gemm_mma<4,0>, cudaFuncAttributeMaxDynamicSharedMemorySize, SMEM_BYTES);
        cudaFuncSetAttribute(gemm_mma<2,1>, cudaFuncAttributeMaxDynamicSharedMemorySize, SMEM_BYTES);
        cudaFuncSetAttribute(gemm_mma<3,1>, cudaFuncAttributeMaxDynamicSharedMemorySize, SMEM_BYTES);
        cudaFuncSetAttribute(gemm_mma<4,1>, cudaFuncAttributeMaxDynamicSharedMemorySize, SMEM_BYTES);
        inited = 1;
    }

    float *wsum, *bsum, *wg;
    __half *x16, *h16, *a16, *w16;
    int *cnt, *rowptr, *cursor, *srcg, *bsums;
    cudaGetSymbolAddress((void**)&x16,    g_x16);
    cudaGetSymbolAddress((void**)&h16,    g_h16);
    cudaGetSymbolAddress((void**)&a16,    g_a16);
    cudaGetSymbolAddress((void**)&cnt,    g_cnt);
    cudaGetSymbolAddress((void**)&rowptr, g_rowptr);
    cudaGetSymbolAddress((void**)&cursor, g_cursor);
    cudaGetSymbolAddress((void**)&srcg,   g_srcg);
    cudaGetSymbolAddress((void**)&wg,     g_wg);
    cudaGetSymbolAddress((void**)&bsums,  g_bsums);
    cudaGetSymbolAddress((void**)&wsum,   g_wsum);
    cudaGetSymbolAddress((void**)&bsum,   g_bsum);
    cudaGetSymbolAddress((void**)&w16,    g_w16);

    const float* xu = (const float*)d_in[0];
    const float* xp = (const float*)d_in[1];
    const float* xc = (const float*)d_in[2];
    const float* xq = (const float*)d_in[3];
    const float* W1l = (const float*)d_in[4];
    const float* b1  = (const float*)d_in[5];
    const float* W1r = (const float*)d_in[6];
    const float* W2l = (const float*)d_in[7];
    const float* b2  = (const float*)d_in[8];
    const float* W2r = (const float*)d_in[9];
    const int* eb  = (const int*)d_in[18];
    const int* es  = (const int*)d_in[19];
    const int* em  = (const int*)d_in[20];
    const int* ein = (const int*)d_in[21];
    float* out = (float*)d_out;

    cudaStream_t st = 0;
    const int NSCAN = (NROWS + 4095) / 4096;

    // ---- fork: prep chain on sx[0], CSR chain on st ----
    cudaEventRecord(ev[0], st);
    cudaStreamWaitEvent(sx[0], ev[0], 0);
    wsum_kernel<<<(2 * 4 * HID * HID + 255) / 256, 256, 0, sx[0]>>>(W1l, b1, W2l, b2, wsum, bsum);
    wconv_kernel<<<(NWCHUNK * HID * HID + 255) / 256, 256, 0, sx[0]>>>(wsum, W1r, W2r, w16);
    xhalf_kernel<<<(NTOT * 16 + 255) / 256, 256, 0, sx[0]>>>(xu, xp, xc, xq, x16);
    cudaEventRecord(ev[1], sx[0]);

    cudaMemsetAsync(cnt, 0, NROWS * sizeof(int), st);
    csr_count<<<(ETOT + 255) / 256, 256, 0, st>>>(eb, es, em, ein, cnt);
    scan1_kernel<<<NSCAN, 256, 0, st>>>(cnt, rowptr, bsums, NROWS);
    scan2_kernel<<<1, 32, 0, st>>>(bsums, NSCAN);
    scan3_kernel<<<NSCAN, 256, 0, st>>>(rowptr, bsums, cursor, NROWS);
    csr_fill<<<(ETOT + 255) / 256, 256, 0, st>>>(
        eb, es, em, ein,
        (const float*)d_in[10], (const float*)d_in[11], (const float*)d_in[12],
        (const float*)d_in[13], (const float*)d_in[14], (const float*)d_in[15],
        (const float*)d_in[16], (const float*)d_in[17],
        cursor, srcg, wg);
    cudaStreamWaitEvent(st, ev[1], 0);   // join

    // ---- two layers ----
    for (int layer = 0; layer < 2; layer++) {
        const __half* src = layer ? h16 : x16;
        gather_kernel<<<((NROWS + 1) / 2 * 32 + 255) / 256, 256, 0, st>>>(
            src, rowptr, srcg, wg, a16);

        int eb_ = 2 + layer * 5;
        cudaEventRecord(ev[eb_], st);
        for (int k = 0; k < 3; k++) cudaStreamWaitEvent(sx[k], ev[eb_], 0);

        static const int dOrder[4] = {1, 0, 3, 2};
        for (int q = 0; q < 4; q++) {
            int d = dOrder[q];
            cudaStream_t gs = (q == 0) ? st : sx[q - 1];

            const __half *Ap[3] = {nullptr, nullptr, nullptr};
            const __half *Wp[4] = {nullptr, nullptr, nullptr, nullptr};
            Wp[0] = w16 + (size_t)(layer * 4 + d) * HID * HID;
            for (int r = 0; r < nRelForDst[d]; r++) {
                int t = relForDst[d][r];
                Ap[r] = a16 + (size_t)rowOffR[t] * HID;
                Wp[r + 1] = w16 + (size_t)(8 + layer * 8 + t) * HID * HID;
            }
            GemmArgs p;
            p.A0 = src + nodeOff[d] * HID;
            p.A1 = Ap[0]; p.A2 = Ap[1]; p.A3 = Ap[2];
            p.W0 = Wp[0]; p.W1 = Wp[1]; p.W2 = Wp[2]; p.W3 = Wp[3];
            int nch = 1 + nRelForDst[d];
            float* C32 = layer ? (out + nodeOff[d] * HID) : nullptr;
            __half* C16 = layer ? nullptr : (h16 + nodeOff[d] * HID);
            const float* bs = bsum + (layer * 4 + d) * HID;
            int grid = (nodeN[d] + 127) / 128;
            if (layer == 0) {
                if (nch == 2)      gemm_mma<2,1><<<grid, 256, SMEM_BYTES, gs>>>(p, bs, C32, C16, nodeN[d]);
                else if (nch == 3) gemm_mma<3,1><<<grid, 256, SMEM_BYTES, gs>>>(p, bs, C32, C16, nodeN[d]);
                else               gemm_mma<4,1><<<grid, 256, SMEM_BYTES, gs>>>(p, bs, C32, C16, nodeN[d]);
            } else {
                if (nch == 2)      gemm_mma<2,0><<<grid, 256, SMEM_BYTES, gs>>>(p, bs, C32, C16, nodeN[d]);
                else if (nch == 3) gemm_mma<3,0><<<grid, 256, SMEM_BYTES, gs>>>(p, bs, C32, C16, nodeN[d]);
                else               gemm_mma<4,0><<<grid, 256, SMEM_BYTES, gs>>>(p, bs, C32, C16, nodeN[d]);
            }
        }
        for (int k = 0; k < 3; k++) {
            cudaEventRecord(ev[eb_ + 1 + k], sx[k]);
            cudaStreamWaitEvent(st, ev[eb_ + 1 + k], 0);
        }
    }
}